// round 4
// baseline (speedup 1.0000x reference)
#include <cuda_runtime.h>
#include <cuda_bf16.h>
#include <stdint.h>
#include <math.h>

// ---------------- constants ----------------
#define NB 64
#define NN 1024
#define NCH 256
#define NR 4
#define NK 1024
#define TOTB 10240
#define PADB 10248

#define OFF_HHAT   0LL
#define OFF_ZQ     16777216LL
#define OFF_IND    33554432LL
#define OFF_IDXHAT 33619968LL
#define OFF_VQ     33685504LL
#define OFF_LOGITS 33685505LL
#define OFF_PROBS  33686273LL
#define OFF_MODE   33687041LL

// ---------------- device scratch ----------------
__device__ int     g_expert[NB];
__device__ int     g_phy[NB];
__device__ float   g_std;
__device__ float   g_zsq[NB * NN];
__device__ float   g_cbsq[NR * NK];
__device__ int     g_indices[NB * NN];
__device__ uint8_t g_bits[NB * PADB];
__device__ double  g_sse;

// ---------------- threefry2x32 (JAX 20-round) ----------------
__device__ __forceinline__ uint32_t rotl32(uint32_t x, int r) {
    return (x << r) | (x >> (32 - r));
}
__device__ __forceinline__ void threefry2x32(uint32_t k0, uint32_t k1,
                                             uint32_t x0, uint32_t x1,
                                             uint32_t& o0, uint32_t& o1) {
    uint32_t k2 = k0 ^ k1 ^ 0x1BD11BDAu;
    x0 += k0; x1 += k1;
#define TF_R(a) x0 += x1; x1 = rotl32(x1, a); x1 ^= x0;
#define TF_G(a,b,c,d) TF_R(a) TF_R(b) TF_R(c) TF_R(d)
    TF_G(13, 15, 26, 6)  x0 += k1; x1 += k2 + 1u;
    TF_G(17, 29, 16, 24) x0 += k2; x1 += k0 + 2u;
    TF_G(13, 15, 26, 6)  x0 += k0; x1 += k1 + 3u;
    TF_G(17, 29, 16, 24) x0 += k1; x1 += k2 + 4u;
    TF_G(13, 15, 26, 6)  x0 += k2; x1 += k0 + 5u;
#undef TF_G
#undef TF_R
    o0 = x0; o1 = x1;
}

// JAX random.normal from raw 32 bits (XLA erf_inv f32, Giles polynomial)
__device__ __forceinline__ float jax_normal_from_bits(uint32_t bits) {
    float u1 = __uint_as_float(0x3f800000u | (bits >> 9)) - 1.0f; // [0,1)
    const float lo = __uint_as_float(0xBF7FFFFFu);                // nextafter(-1,0)
    float u = __fadd_rn(__fmul_rn(u1, 2.0f), lo);                 // (hi-lo) rounds to 2.0f
    u = fmaxf(u, lo);
    float x2 = __fmul_rn(u, u);
    float w = -log1pf(-x2);
    float p;
    if (w < 5.0f) {
        w = __fsub_rn(w, 2.5f);
        p = 2.81022636e-08f;
        p = __fmaf_rn(p, w, 3.43273939e-07f);
        p = __fmaf_rn(p, w, -3.5233877e-06f);
        p = __fmaf_rn(p, w, -4.39150654e-06f);
        p = __fmaf_rn(p, w, 0.00021858087f);
        p = __fmaf_rn(p, w, -0.00125372503f);
        p = __fmaf_rn(p, w, -0.00417768164f);
        p = __fmaf_rn(p, w, 0.246640727f);
        p = __fmaf_rn(p, w, 1.50140941f);
    } else {
        w = __fsub_rn(sqrtf(w), 3.0f);
        p = -0.000200214257f;
        p = __fmaf_rn(p, w, 0.000100950558f);
        p = __fmaf_rn(p, w, 0.00134934322f);
        p = __fmaf_rn(p, w, -0.00367342844f);
        p = __fmaf_rn(p, w, 0.00573950773f);
        p = __fmaf_rn(p, w, -0.0076224613f);
        p = __fmaf_rn(p, w, 0.00943887047f);
        p = __fmaf_rn(p, w, 1.00167406f);
        p = __fmaf_rn(p, w, 2.83297682f);
    }
    float ei = __fmul_rn(p, u);
    return __fmul_rn(__uint_as_float(0x3FB504F3u) /* f32 sqrt(2) */, ei);
}

// jax_threefry_partitionable=True stream (modern JAX default):
// element i (size <= 2^32): counter = (0, i); 32-bit output = o0 ^ o1.
__device__ __forceinline__ float gen_normal_part(uint32_t k0, uint32_t k1, uint32_t i) {
    uint32_t o0, o1;
    threefry2x32(k0, k1, 0u, i, o0, o1);
    return jax_normal_from_bits(o0 ^ o1);
}

// ---------------- K1: router MLP + softmax + argmax ----------------
__global__ void __launch_bounds__(128) mlp_kernel(
    const float* __restrict__ phi, const float* __restrict__ w0,
    const float* __restrict__ b0, const float* __restrict__ w1,
    const float* __restrict__ b1, const float* __restrict__ w2,
    const float* __restrict__ b2, const float* __restrict__ noise_var,
    float* __restrict__ out) {
    __shared__ float sphi[512], sh[128], sh2[128], sl[12];
    int b = blockIdx.x, t = threadIdx.x;
    if (b == 0 && t == 0) g_sse = 0.0;
    for (int d = t; d < 512; d += 128) sphi[d] = phi[b * 512 + d];
    __syncthreads();
    float a = 0.f;
    #pragma unroll 8
    for (int d = 0; d < 512; d++) a = __fmaf_rn(sphi[d], w0[d * 128 + t], a);
    sh[t] = fmaxf(__fadd_rn(a, b0[t]), 0.f);
    __syncthreads();
    float a2 = 0.f;
    #pragma unroll 8
    for (int i = 0; i < 128; i++) a2 = __fmaf_rn(sh[i], w1[i * 128 + t], a2);
    sh2[t] = fmaxf(__fadd_rn(a2, b1[t]), 0.f);
    __syncthreads();
    if (t < 12) {
        float l = 0.f;
        for (int i = 0; i < 128; i++) l = __fmaf_rn(sh2[i], w2[i * 12 + t], l);
        l = __fadd_rn(l, b2[t]);
        sl[t] = l;
        out[OFF_LOGITS + b * 12 + t] = l;
    }
    __syncthreads();
    if (t == 0) {
        float mx = sl[0]; int mi = 0;
        for (int j = 1; j < 12; j++) if (sl[j] > mx) { mx = sl[j]; mi = j; }
        float e[12], s = 0.f;
        for (int j = 0; j < 12; j++) { e[j] = expf(__fsub_rn(sl[j], mx)); s = __fadd_rn(s, e[j]); }
        for (int j = 0; j < 12; j++) out[OFF_PROBS + b * 12 + j] = __fdiv_rn(e[j], s);
        out[OFF_MODE + b] = (float)mi;
        g_expert[b] = mi / 3;
        g_phy[b] = mi % 3;
        if (b == 0) g_std = sqrtf(fmaxf(noise_var[0], 0.f));
    }
}

// ---------------- K2: squared row norms ----------------
__global__ void __launch_bounds__(256) sq_kernel(const float* __restrict__ H,
                                                 const float* __restrict__ cb) {
    int warp = (blockIdx.x * blockDim.x + threadIdx.x) >> 5;
    int lane = threadIdx.x & 31;
    const int TOT = NB * NN + NR * NK;
    if (warp >= TOT) return;
    const float* src = (warp < NB * NN) ? (H + (size_t)warp * NCH)
                                        : (cb + (size_t)(warp - NB * NN) * NCH);
    double s = 0.0;
    #pragma unroll
    for (int c = lane; c < NCH; c += 32) {
        float v = src[c];
        s += (double)__fmul_rn(v, v);
    }
    #pragma unroll
    for (int off = 16; off; off >>= 1) s += __shfl_down_sync(0xffffffffu, s, off);
    if (lane == 0) {
        if (warp < NB * NN) g_zsq[warp] = (float)s;
        else g_cbsq[warp - NB * NN] = (float)s;
    }
}

// ---------------- K3: fused distance GEMM + argmin ----------------
#define VQ_BK 32
#define VQ_PAD 132

__global__ void __launch_bounds__(256, 2) vq_kernel(const float* __restrict__ H,
                                                    const float* __restrict__ codebooks) {
    __shared__ float As[VQ_BK][VQ_PAD];
    __shared__ float Bs[VQ_BK][VQ_PAD];

    int tid = threadIdx.x;
    int tx = tid & 15;
    int ty = tid >> 4;
    int row0 = blockIdx.x * 128;
    int b = row0 >> 10;
    int r = g_expert[b];
    const float* zbase = H + (size_t)row0 * NCH;
    const float* cbbase = codebooks + (size_t)r * NK * NCH;
    const float* cbsq = g_cbsq + r * NK;

    float zs[8];
    #pragma unroll
    for (int i = 0; i < 8; i++) zs[i] = g_zsq[row0 + ty * 8 + i];

    float minv[8]; int mini[8];
    #pragma unroll
    for (int i = 0; i < 8; i++) { minv[i] = 3.402823466e+38f; mini[i] = 0; }

    for (int cw0 = 0; cw0 < NK; cw0 += 128) {
        float acc[8][8];
        #pragma unroll
        for (int i = 0; i < 8; i++)
            #pragma unroll
            for (int j = 0; j < 8; j++) acc[i][j] = 0.f;

        float cbs[8];
        #pragma unroll
        for (int j = 0; j < 8; j++) cbs[j] = cbsq[cw0 + tx * 8 + j];

        for (int kt = 0; kt < NCH; kt += VQ_BK) {
            #pragma unroll
            for (int q = 0; q < 4; q++) {
                int l = tid + q * 256;
                int mr = l >> 3;
                int k4 = (l & 7) << 2;
                float4 v = *reinterpret_cast<const float4*>(zbase + (size_t)mr * NCH + kt + k4);
                As[k4 + 0][mr] = v.x; As[k4 + 1][mr] = v.y;
                As[k4 + 2][mr] = v.z; As[k4 + 3][mr] = v.w;
                float4 u = *reinterpret_cast<const float4*>(cbbase + (size_t)(cw0 + mr) * NCH + kt + k4);
                Bs[k4 + 0][mr] = u.x; Bs[k4 + 1][mr] = u.y;
                Bs[k4 + 2][mr] = u.z; Bs[k4 + 3][mr] = u.w;
            }
            __syncthreads();
            #pragma unroll
            for (int kk = 0; kk < VQ_BK; kk++) {
                float4 a0 = *reinterpret_cast<const float4*>(&As[kk][ty * 8]);
                float4 a1 = *reinterpret_cast<const float4*>(&As[kk][ty * 8 + 4]);
                float4 b0v = *reinterpret_cast<const float4*>(&Bs[kk][tx * 8]);
                float4 b1v = *reinterpret_cast<const float4*>(&Bs[kk][tx * 8 + 4]);
                float av[8] = {a0.x, a0.y, a0.z, a0.w, a1.x, a1.y, a1.z, a1.w};
                float bv[8] = {b0v.x, b0v.y, b0v.z, b0v.w, b1v.x, b1v.y, b1v.z, b1v.w};
                #pragma unroll
                for (int i = 0; i < 8; i++)
                    #pragma unroll
                    for (int j = 0; j < 8; j++)
                        acc[i][j] = __fmaf_rn(av[i], bv[j], acc[i][j]);
            }
            __syncthreads();
        }
        #pragma unroll
        for (int i = 0; i < 8; i++) {
            #pragma unroll
            for (int j = 0; j < 8; j++) {
                float s = __fadd_rn(zs[i], cbs[j]);
                float d = __fmaf_rn(-2.0f, acc[i][j], s);
                if (d < minv[i]) { minv[i] = d; mini[i] = cw0 + tx * 8 + j; }
            }
        }
    }

    #pragma unroll
    for (int i = 0; i < 8; i++) {
        float v = minv[i]; int ix = mini[i];
        #pragma unroll
        for (int off = 8; off; off >>= 1) {
            float ov = __shfl_down_sync(0xffffffffu, v, off, 16);
            int oi = __shfl_down_sync(0xffffffffu, ix, off, 16);
            if (ov < v || (ov == v && oi < ix)) { v = ov; ix = oi; }
        }
        if (tx == 0) g_indices[row0 + ty * 8 + i] = ix;
    }
}

// ---------------- K4: z_q gather + straight-through + SSE + indices ----------------
__global__ void __launch_bounds__(256) zq_kernel(const float* __restrict__ H,
                                                 const float* __restrict__ codebooks,
                                                 float* __restrict__ out) {
    __shared__ int sidx[128];
    __shared__ double red[256];
    int blk = blockIdx.x, tid = threadIdx.x;
    int row0 = blk * 128;
    int b = row0 >> 10;
    int r = g_expert[b];
    if (tid < 128) {
        int row = row0 + tid;
        int v = g_indices[row];
        sidx[tid] = v;
        out[OFF_IND + row] = (float)v;
    }
    __syncthreads();
    double acc = 0.0;
    int c = tid;
    for (int i = 0; i < 128; i++) {
        size_t row = (size_t)row0 + i;
        float h = H[row * NCH + c];
        float q = codebooks[((size_t)r * NK + sidx[i]) * NCH + c];
        float dlt = __fsub_rn(q, h);
        out[OFF_ZQ + row * NCH + c] = __fadd_rn(h, dlt);
        float sq = __fmul_rn(dlt, dlt);
        acc += (double)sq;
    }
    red[tid] = acc;
    __syncthreads();
    for (int s = 128; s; s >>= 1) {
        if (tid < s) red[tid] += red[tid + s];
        __syncthreads();
    }
    if (tid == 0) atomicAdd(&g_sse, red[0]);
}

// ---------------- K5: QAM channel (mod + partitionable-threefry noise + demod) ----------------
__global__ void __launch_bounds__(256) channel_kernel() {
    int b = blockIdx.x;
    int m = g_phy[b];
    int bps = (m == 0) ? 2 : (m == 1) ? 4 : 6;
    int n_sym = PADB / bps;
    int mside = (m == 0) ? 2 : (m == 1) ? 4 : 8;
    int M = mside * mside;
    float std_ = g_std;

    __shared__ float cx[64], cy[64];
    __shared__ uint32_t skey[2];
    if (threadIdx.x < M) {
        double mean = (m == 0) ? 2.0 : (m == 1) ? 10.0 : 42.0;
        double norm = sqrt(mean + 1e-9);
        int i = threadIdx.x / mside, j = threadIdx.x % mside;
        cx[threadIdx.x] = (float)((double)(-(mside - 1) + 2 * i) / norm);
        cy[threadIdx.x] = (float)((double)(-(mside - 1) + 2 * j) / norm);
    }
    if (threadIdx.x == 0) {
        uint32_t o0, o1;
        threefry2x32(0u, 42u, 0u, (uint32_t)m, o0, o1); // fold_in(key(42), m)
        skey[0] = o0; skey[1] = o1;
    }
    __syncthreads();
    uint32_t k0 = skey[0], k1 = skey[1];
    const int* idxrow = g_indices + b * NN;
    uint8_t* bitrow = g_bits + b * PADB;

    for (int s = threadIdx.x; s < n_sym; s += 256) {
        int p0 = s * bps;
        int sym = 0;
        for (int j = 0; j < bps; j++) {
            int p = p0 + j;
            int bit = 0;
            if (p < TOTB) bit = (idxrow[p / 10] >> (9 - p % 10)) & 1;
            sym = (sym << 1) | bit;
        }
        float tx0 = cx[sym], tx1 = cy[sym];
        uint32_t i0 = (uint32_t)(b * n_sym + s) * 2u;
        float n0 = gen_normal_part(k0, k1, i0);
        float n1 = gen_normal_part(k0, k1, i0 + 1u);
        // reference: rx = tx + std*noise (mul and add separately rounded)
        float rx0 = __fadd_rn(tx0, __fmul_rn(std_, n0));
        float rx1 = __fadd_rn(tx1, __fmul_rn(std_, n1));
        float best = 3.402823466e+38f; int bi = 0;
        for (int k = 0; k < M; k++) {
            float dx = __fsub_rn(rx0, cx[k]);
            float dy = __fsub_rn(rx1, cy[k]);
            float d = __fadd_rn(__fmul_rn(dx, dx), __fmul_rn(dy, dy));
            if (d < best) { best = d; bi = k; }
        }
        for (int j = 0; j < bps; j++)
            bitrow[p0 + j] = (uint8_t)((bi >> (bps - 1 - j)) & 1);
    }
}

// ---------------- K6: idx_hat recompose + H_hat gather + vq_loss ----------------
__global__ void __launch_bounds__(256) final_kernel(const float* __restrict__ H,
                                                    const float* __restrict__ codebooks,
                                                    float* __restrict__ out) {
    __shared__ int sidx[128];
    int blk = blockIdx.x, tid = threadIdx.x;
    int row0 = blk * 128;
    int b = row0 >> 10;
    int r = g_expert[b];
    if (tid < 128) {
        int row = row0 + tid;
        int n = row & (NN - 1);
        const uint8_t* bt = g_bits + b * PADB + n * 10;
        int v = 0;
        #pragma unroll
        for (int j = 0; j < 10; j++) v = (v << 1) | bt[j];
        if (v > NK - 1) v = NK - 1;
        if (v < 0) v = 0;
        sidx[tid] = v;
        out[OFF_IDXHAT + row] = (float)v;
    }
    __syncthreads();
    int c = tid;
    for (int i = 0; i < 128; i++) {
        size_t row = (size_t)row0 + i;
        float h = H[row * NCH + c];
        float cbv = codebooks[((size_t)r * NK + sidx[i]) * NCH + c];
        out[OFF_HHAT + row * NCH + c] = __fadd_rn(h, __fsub_rn(cbv, h));
    }
    if (blk == 0 && tid == 0) {
        double denom = (double)NB * (double)NN * (double)NCH * (double)NCH;
        out[OFF_VQ] = (float)(1.25 * g_sse / denom);
    }
}

// ---------------- launch ----------------
extern "C" void kernel_launch(void* const* d_in, const int* in_sizes, int n_in,
                              void* d_out, int out_size) {
    const float* H         = (const float*)d_in[0];
    const float* phi       = (const float*)d_in[1];
    const float* w0        = (const float*)d_in[2];
    const float* b0        = (const float*)d_in[3];
    const float* w1        = (const float*)d_in[4];
    const float* b1        = (const float*)d_in[5];
    const float* w2        = (const float*)d_in[6];
    const float* b2        = (const float*)d_in[7];
    const float* codebooks = (const float*)d_in[8];
    const float* noise_var = (const float*)d_in[9];
    float* out = (float*)d_out;

    mlp_kernel<<<NB, 128>>>(phi, w0, b0, w1, b1, w2, b2, noise_var, out);

    int warps = NB * NN + NR * NK;
    sq_kernel<<<(warps + 7) / 8, 256>>>(H, codebooks);

    vq_kernel<<<(NB * NN) / 128, 256>>>(H, codebooks);

    zq_kernel<<<(NB * NN) / 128, 256>>>(H, codebooks, out);

    channel_kernel<<<NB, 256>>>();

    final_kernel<<<(NB * NN) / 128, 256>>>(H, codebooks, out);
}

// round 8
// speedup vs baseline: 1.4664x; 1.4664x over previous
#include <cuda_runtime.h>
#include <cuda_bf16.h>
#include <stdint.h>
#include <math.h>

#define NB 64
#define NN 1024
#define NCH 256
#define NR 4
#define NK 1024
#define TOTB 10240
#define PADB 10248
#define EPSF 0.5f
#define MARG 2e-4f
#define CCAP 128

#define OFF_HHAT   0LL
#define OFF_ZQ     16777216LL
#define OFF_IND    33554432LL
#define OFF_IDXHAT 33619968LL
#define OFF_VQ     33685504LL
#define OFF_LOGITS 33685505LL
#define OFF_PROBS  33686273LL
#define OFF_MODE   33687041LL

__device__ int     g_expert[NB];
__device__ int     g_phy[NB];
__device__ float   g_std;
__device__ float   g_zsq[NB * NN];
__device__ float   g_cbsq[NR * NK];
__device__ int     g_indices[NB * NN];
__device__ uint8_t g_bits[NB * PADB];
__device__ double  g_sse;
__device__ __align__(16) __nv_bfloat16 g_Hb[NB * NN * NCH];
__device__ __align__(16) __nv_bfloat16 g_cbb[NR * NK * NCH];
__device__ int   g_cand[(size_t)NB * NN * CCAP];
__device__ int   g_cc[NB * NN];

// ---- mma / ldmatrix helpers ----
__device__ __forceinline__ uint32_t smem_to_u32(const void* p) {
    uint32_t a;
    asm("{ .reg .u64 t; cvta.to.shared.u64 t, %1; cvt.u32.u64 %0, t; }" : "=r"(a) : "l"(p));
    return a;
}
__device__ __forceinline__ void ldmx4(uint32_t* r, uint32_t addr) {
    asm volatile("ldmatrix.sync.aligned.m8n8.x4.shared.b16 {%0,%1,%2,%3}, [%4];"
        : "=r"(r[0]), "=r"(r[1]), "=r"(r[2]), "=r"(r[3]) : "r"(addr));
}
__device__ __forceinline__ void ldmx2(uint32_t* r, uint32_t addr) {
    asm volatile("ldmatrix.sync.aligned.m8n8.x2.shared.b16 {%0,%1}, [%2];"
        : "=r"(r[0]), "=r"(r[1]) : "r"(addr));
}
__device__ __forceinline__ void mma_bf16(float* c, const uint32_t* a, const uint32_t* b) {
    asm volatile("mma.sync.aligned.m16n8k16.row.col.f32.bf16.bf16.f32 "
        "{%0,%1,%2,%3}, {%4,%5,%6,%7}, {%8,%9}, {%0,%1,%2,%3};"
        : "+f"(c[0]), "+f"(c[1]), "+f"(c[2]), "+f"(c[3])
        : "r"(a[0]), "r"(a[1]), "r"(a[2]), "r"(a[3]), "r"(b[0]), "r"(b[1]));
}

// ---- threefry (JAX) ----
__device__ __forceinline__ uint32_t rotl32(uint32_t x, int r) { return (x << r) | (x >> (32 - r)); }
__device__ __forceinline__ void threefry2x32(uint32_t k0, uint32_t k1, uint32_t x0, uint32_t x1,
                                             uint32_t& o0, uint32_t& o1) {
    uint32_t k2 = k0 ^ k1 ^ 0x1BD11BDAu;
    x0 += k0; x1 += k1;
#define TF_R(a) x0 += x1; x1 = rotl32(x1, a); x1 ^= x0;
#define TF_G(a,b,c,d) TF_R(a) TF_R(b) TF_R(c) TF_R(d)
    TF_G(13, 15, 26, 6)  x0 += k1; x1 += k2 + 1u;
    TF_G(17, 29, 16, 24) x0 += k2; x1 += k0 + 2u;
    TF_G(13, 15, 26, 6)  x0 += k0; x1 += k1 + 3u;
    TF_G(17, 29, 16, 24) x0 += k1; x1 += k2 + 4u;
    TF_G(13, 15, 26, 6)  x0 += k2; x1 += k0 + 5u;
#undef TF_G
#undef TF_R
    o0 = x0; o1 = x1;
}
__device__ __forceinline__ float jax_normal_from_bits(uint32_t bits) {
    float u1 = __uint_as_float(0x3f800000u | (bits >> 9)) - 1.0f;
    const float lo = __uint_as_float(0xBF7FFFFFu);
    float u = __fadd_rn(__fmul_rn(u1, 2.0f), lo);
    u = fmaxf(u, lo);
    float w = -log1pf(-__fmul_rn(u, u));
    float p;
    if (w < 5.0f) {
        w = __fsub_rn(w, 2.5f);
        p = 2.81022636e-08f;
        p = __fmaf_rn(p, w, 3.43273939e-07f);
        p = __fmaf_rn(p, w, -3.5233877e-06f);
        p = __fmaf_rn(p, w, -4.39150654e-06f);
        p = __fmaf_rn(p, w, 0.00021858087f);
        p = __fmaf_rn(p, w, -0.00125372503f);
        p = __fmaf_rn(p, w, -0.00417768164f);
        p = __fmaf_rn(p, w, 0.246640727f);
        p = __fmaf_rn(p, w, 1.50140941f);
    } else {
        w = __fsub_rn(sqrtf(w), 3.0f);
        p = -0.000200214257f;
        p = __fmaf_rn(p, w, 0.000100950558f);
        p = __fmaf_rn(p, w, 0.00134934322f);
        p = __fmaf_rn(p, w, -0.00367342844f);
        p = __fmaf_rn(p, w, 0.00573950773f);
        p = __fmaf_rn(p, w, -0.0076224613f);
        p = __fmaf_rn(p, w, 0.00943887047f);
        p = __fmaf_rn(p, w, 1.00167406f);
        p = __fmaf_rn(p, w, 2.83297682f);
    }
    return __fmul_rn(__uint_as_float(0x3FB504F3u), __fmul_rn(p, u));
}
__device__ __forceinline__ float gen_normal_part(uint32_t k0, uint32_t k1, uint32_t i) {
    uint32_t o0, o1;
    threefry2x32(k0, k1, 0u, i, o0, o1);
    return jax_normal_from_bits(o0 ^ o1);
}

// ---- K0: bf16 convert ----
__global__ void __launch_bounds__(256) prep_kernel(const float* __restrict__ H,
                                                   const float* __restrict__ cb) {
    int i = blockIdx.x * 256 + threadIdx.x;
    const int NH4 = NB * NN * NCH / 4, NC4 = NR * NK * NCH / 4;
    if (i < NH4) {
        float4 v = reinterpret_cast<const float4*>(H)[i];
        __nv_bfloat162 p0 = __floats2bfloat162_rn(v.x, v.y), p1 = __floats2bfloat162_rn(v.z, v.w);
        reinterpret_cast<uint2*>(g_Hb)[i] = make_uint2(*(uint32_t*)&p0, *(uint32_t*)&p1);
    } else if (i - NH4 < NC4) {
        int j = i - NH4;
        float4 v = reinterpret_cast<const float4*>(cb)[j];
        __nv_bfloat162 p0 = __floats2bfloat162_rn(v.x, v.y), p1 = __floats2bfloat162_rn(v.z, v.w);
        reinterpret_cast<uint2*>(g_cbb)[j] = make_uint2(*(uint32_t*)&p0, *(uint32_t*)&p1);
    }
}

// ---- K1: router MLP ----
__global__ void __launch_bounds__(128) mlp_kernel(
    const float* __restrict__ phi, const float* __restrict__ w0, const float* __restrict__ b0,
    const float* __restrict__ w1, const float* __restrict__ b1, const float* __restrict__ w2,
    const float* __restrict__ b2, const float* __restrict__ noise_var, float* __restrict__ out) {
    __shared__ float sphi[512], sh[128], sh2[128], sl[12];
    int b = blockIdx.x, t = threadIdx.x;
    if (b == 0 && t == 0) g_sse = 0.0;
    for (int d = t; d < 512; d += 128) sphi[d] = phi[b * 512 + d];
    __syncthreads();
    float a = 0.f;
    #pragma unroll 8
    for (int d = 0; d < 512; d++) a = __fmaf_rn(sphi[d], w0[d * 128 + t], a);
    sh[t] = fmaxf(__fadd_rn(a, b0[t]), 0.f);
    __syncthreads();
    float a2 = 0.f;
    #pragma unroll 8
    for (int i = 0; i < 128; i++) a2 = __fmaf_rn(sh[i], w1[i * 128 + t], a2);
    sh2[t] = fmaxf(__fadd_rn(a2, b1[t]), 0.f);
    __syncthreads();
    if (t < 12) {
        float l = 0.f;
        for (int i = 0; i < 128; i++) l = __fmaf_rn(sh2[i], w2[i * 12 + t], l);
        l = __fadd_rn(l, b2[t]);
        sl[t] = l;
        out[OFF_LOGITS + b * 12 + t] = l;
    }
    __syncthreads();
    if (t == 0) {
        float mx = sl[0]; int mi = 0;
        for (int j = 1; j < 12; j++) if (sl[j] > mx) { mx = sl[j]; mi = j; }
        float e[12], s = 0.f;
        for (int j = 0; j < 12; j++) { e[j] = expf(__fsub_rn(sl[j], mx)); s = __fadd_rn(s, e[j]); }
        for (int j = 0; j < 12; j++) out[OFF_PROBS + b * 12 + j] = __fdiv_rn(e[j], s);
        out[OFF_MODE + b] = (float)mi;
        g_expert[b] = mi / 3;
        g_phy[b] = mi % 3;
        if (b == 0) g_std = sqrtf(fmaxf(noise_var[0], 0.f));
    }
}

// ---- K2: row squared norms ----
__global__ void __launch_bounds__(256) sq_kernel(const float* __restrict__ H,
                                                 const float* __restrict__ cb) {
    int warp = (blockIdx.x * blockDim.x + threadIdx.x) >> 5;
    int lane = threadIdx.x & 31;
    const int TOT = NB * NN + NR * NK;
    if (warp >= TOT) return;
    const float* src = (warp < NB * NN) ? (H + (size_t)warp * NCH) : (cb + (size_t)(warp - NB * NN) * NCH);
    double s = 0.0;
    #pragma unroll
    for (int c = lane; c < NCH; c += 32) { float v = src[c]; s += (double)__fmul_rn(v, v); }
    #pragma unroll
    for (int o = 16; o; o >>= 1) s += __shfl_down_sync(0xffffffffu, s, o);
    if (lane == 0) { if (warp < NB * NN) g_zsq[warp] = (float)s; else g_cbsq[warp - NB * NN] = (float)s; }
}

// ---- K3: bf16 mma.sync distance GEMM + candidate filter ----
#define SM_ZSQ 0
#define SM_CBSQ 512
#define SM_MIN 4608
#define SM_CNT 5120
#define SM_AS 5632
#define SM_BS 15872
#define SM_DS 26112
#define SM_TOT 93696

__global__ void __launch_bounds__(256, 2) vqm_kernel() {
    extern __shared__ char smem[];
    float* zsq_s = (float*)(smem + SM_ZSQ);
    float* cbsq_s = (float*)(smem + SM_CBSQ);
    float* minv_s = (float*)(smem + SM_MIN);
    int* cnt_s = (int*)(smem + SM_CNT);
    __nv_bfloat16* As = (__nv_bfloat16*)(smem + SM_AS);
    __nv_bfloat16* Bs = (__nv_bfloat16*)(smem + SM_BS);
    float* Ds = (float*)(smem + SM_DS);

    int tid = threadIdx.x, wid = tid >> 5, lane = tid & 31;
    int row0 = blockIdx.x * 128;
    int r = g_expert[row0 >> 10];
    if (tid < 128) { zsq_s[tid] = g_zsq[row0 + tid]; minv_s[tid] = 3.402823466e+38f; cnt_s[tid] = 0; }
    for (int j = tid; j < 1024; j += 256) cbsq_s[j] = g_cbsq[r * 1024 + j];
    __syncthreads();

    int warp_m = wid & 3, warp_n = wid >> 2;
    uint32_t as_b = smem_to_u32(As), bs_b = smem_to_u32(Bs);

    for (int ch = 0; ch < 8; ch++) {
        float acc[2][8][4];
        #pragma unroll
        for (int mf = 0; mf < 2; mf++)
            #pragma unroll
            for (int nf = 0; nf < 8; nf++)
                #pragma unroll
                for (int v = 0; v < 4; v++) acc[mf][nf][v] = 0.f;

        for (int kt = 0; kt < 8; kt++) {
            __syncthreads();
            #pragma unroll
            for (int q = 0; q < 2; q++) {
                int u = tid * 2 + q;
                int rr = u >> 2, kk = (u & 3) * 8;
                *(uint4*)(As + rr * 40 + kk) =
                    *(const uint4*)(g_Hb + (size_t)(row0 + rr) * 256 + kt * 32 + kk);
                *(uint4*)(Bs + rr * 40 + kk) =
                    *(const uint4*)(g_cbb + (size_t)(r * 1024 + ch * 128 + rr) * 256 + kt * 32 + kk);
            }
            __syncthreads();
            #pragma unroll
            for (int ks = 0; ks < 2; ks++) {
                int kcol = ks * 16;
                uint32_t af[2][4], bfr[8][2];
                #pragma unroll
                for (int mf = 0; mf < 2; mf++) {
                    int arow = warp_m * 32 + mf * 16 + (lane & 7) + ((lane >> 3) & 1) * 8;
                    int acol = kcol + (lane >> 4) * 8;
                    ldmx4(af[mf], as_b + (uint32_t)(arow * 40 + acol) * 2);
                }
                #pragma unroll
                for (int nf = 0; nf < 8; nf++) {
                    int l = lane & 15;
                    int brow = warp_n * 64 + nf * 8 + (l & 7);
                    int bcol = kcol + ((l >> 3) & 1) * 8;
                    ldmx2(bfr[nf], bs_b + (uint32_t)(brow * 40 + bcol) * 2);
                }
                #pragma unroll
                for (int mf = 0; mf < 2; mf++)
                    #pragma unroll
                    for (int nf = 0; nf < 8; nf++)
                        mma_bf16(acc[mf][nf], af[mf], bfr[nf]);
            }
        }
        __syncthreads();
        #pragma unroll
        for (int mf = 0; mf < 2; mf++) {
            int mrow = warp_m * 32 + mf * 16 + (lane >> 2);
            #pragma unroll
            for (int nf = 0; nf < 8; nf++) {
                int ncol = warp_n * 64 + nf * 8 + (lane & 3) * 2;
                Ds[mrow * 132 + ncol] = acc[mf][nf][0];
                Ds[mrow * 132 + ncol + 1] = acc[mf][nf][1];
                Ds[(mrow + 8) * 132 + ncol] = acc[mf][nf][2];
                Ds[(mrow + 8) * 132 + ncol + 1] = acc[mf][nf][3];
            }
        }
        __syncthreads();
        for (int i = 0; i < 16; i++) {
            int row = wid * 16 + i;
            float zq = zsq_s[row];
            float d[4];
            #pragma unroll
            for (int v = 0; v < 4; v++) {
                int c = lane + v * 32;
                d[v] = __fmaf_rn(-2.0f, Ds[row * 132 + c], __fadd_rn(zq, cbsq_s[ch * 128 + c]));
            }
            float mn = fminf(fminf(d[0], d[1]), fminf(d[2], d[3]));
            #pragma unroll
            for (int o = 16; o; o >>= 1) mn = fminf(mn, __shfl_xor_sync(0xffffffffu, mn, o));
            float nm = fminf(minv_s[row], mn);
            float thr = nm + EPSF;
            int base = cnt_s[row];
            #pragma unroll
            for (int v = 0; v < 4; v++) {
                bool p = d[v] <= thr;
                uint32_t mask = __ballot_sync(0xffffffffu, p);
                int off = base + __popc(mask & ((1u << lane) - 1u));
                if (p && off < CCAP)
                    g_cand[(size_t)(row0 + row) * CCAP + off] = ch * 128 + lane + v * 32;
                base += __popc(mask);
            }
            if (lane == 0) { minv_s[row] = nm; cnt_s[row] = base; }
            __syncwarp();
        }
        __syncthreads();
    }
    if (tid < 128) g_cc[row0 + tid] = cnt_s[tid];
}

// ---- K3b: exact re-rank (tree prefilter + R3-ordering sequential decisive compare) ----
__device__ __forceinline__ float tree_d(const float* __restrict__ cr, const float zr[8],
                                        int lane, float zsqv, float cbsqj) {
    float p = 0.f;
    #pragma unroll
    for (int t = 0; t < 8; t++) p = __fmaf_rn(zr[t], cr[lane + 32 * t], p);
    #pragma unroll
    for (int o = 16; o; o >>= 1) p += __shfl_xor_sync(0xffffffffu, p, o);
    return __fmaf_rn(-2.0f, p, __fadd_rn(zsqv, cbsqj));
}
// Sequential k=0..255 FMA chain — bit-identical to the Round-3 kernel that passed.
__device__ __forceinline__ float seq_d(const float* __restrict__ z, const float* __restrict__ cr,
                                       float zsqv, float cbsqj) {
    float acc = 0.f;
    #pragma unroll 8
    for (int k = 0; k < 256; k++) acc = __fmaf_rn(z[k], cr[k], acc);
    return __fmaf_rn(-2.0f, acc, __fadd_rn(zsqv, cbsqj));
}
__global__ void __launch_bounds__(256) p2_kernel(const float* __restrict__ H,
                                                 const float* __restrict__ cb) {
    int wid = threadIdx.x >> 5, lane = threadIdx.x & 31;
    int row = blockIdx.x * 8 + wid;
    int r = g_expert[row >> 10];
    const float* z = H + (size_t)row * 256;
    const float* cbase = cb + (size_t)r * 1024 * 256;
    const float* cbsq = g_cbsq + r * 1024;
    float zr[8];
    #pragma unroll
    for (int t = 0; t < 8; t++) zr[t] = z[lane + 32 * t];
    float zsqv = g_zsq[row];
    int c = g_cc[row];
    bool full = (c > CCAP);
    int n = full ? 1024 : c;
    const int* cl = g_cand + (size_t)row * CCAP;

    // pass A: fast tree-dot min
    float dmin = 3.402823466e+38f;
    for (int i = 0; i < n; i++) {
        int j = full ? i : cl[i];
        float d = tree_d(cbase + (size_t)j * 256, zr, lane, zsqv, cbsq[j]);
        dmin = fminf(dmin, d);
    }
    // pass B: exact sequential compare for near-ties
    float thr = dmin + MARG;
    float best = 3.402823466e+38f; int bestj = 0x7fffffff;
    for (int i = 0; i < n; i++) {
        int j = full ? i : cl[i];
        float d = tree_d(cbase + (size_t)j * 256, zr, lane, zsqv, cbsq[j]);
        if (d <= thr) {
            float ds = seq_d(z, cbase + (size_t)j * 256, zsqv, cbsq[j]);
            if (ds < best || (ds == best && j < bestj)) { best = ds; bestj = j; }
        }
    }
    if (lane == 0) g_indices[row] = bestj;
}

// ---- K4: z_q + SSE + indices ----
__global__ void __launch_bounds__(256) zq_kernel(const float* __restrict__ H,
                                                 const float* __restrict__ cb,
                                                 float* __restrict__ out) {
    __shared__ int sidx[16];
    __shared__ double red[256];
    int t = threadIdx.x;
    int row0 = blockIdx.x * 16;
    int r = g_expert[row0 >> 10];
    if (t < 16) {
        int row = row0 + t;
        int v = g_indices[row];
        sidx[t] = v;
        out[OFF_IND + row] = (float)v;
    }
    __syncthreads();
    double acc = 0.0;
    #pragma unroll
    for (int it = 0; it < 4; it++) {
        int qid = it * 256 + t;
        int rl = qid >> 6, qq = qid & 63;
        size_t row = (size_t)row0 + rl;
        float4 h = reinterpret_cast<const float4*>(H)[row * 64 + qq];
        float4 q = reinterpret_cast<const float4*>(cb)[((size_t)r * 1024 + sidx[rl]) * 64 + qq];
        float dx = __fsub_rn(q.x, h.x), dy = __fsub_rn(q.y, h.y);
        float dz = __fsub_rn(q.z, h.z), dw = __fsub_rn(q.w, h.w);
        reinterpret_cast<float4*>(out + OFF_ZQ)[row * 64 + qq] =
            make_float4(__fadd_rn(h.x, dx), __fadd_rn(h.y, dy), __fadd_rn(h.z, dz), __fadd_rn(h.w, dw));
        acc += (double)__fmul_rn(dx, dx) + (double)__fmul_rn(dy, dy)
             + (double)__fmul_rn(dz, dz) + (double)__fmul_rn(dw, dw);
    }
    red[t] = acc;
    __syncthreads();
    for (int s = 128; s; s >>= 1) { if (t < s) red[t] += red[t + s]; __syncthreads(); }
    if (t == 0) atomicAdd(&g_sse, red[0]);
}

// ---- K5: QAM channel ----
__global__ void __launch_bounds__(256) channel_kernel() {
    int b = blockIdx.x;
    int m = g_phy[b];
    int bps = (m == 0) ? 2 : (m == 1) ? 4 : 6;
    int n_sym = PADB / bps;
    int mside = (m == 0) ? 2 : (m == 1) ? 4 : 8;
    int M = mside * mside;
    float std_ = g_std;
    __shared__ float cx[64], cy[64];
    __shared__ uint32_t skey[2];
    if (threadIdx.x < M) {
        double mean = (m == 0) ? 2.0 : (m == 1) ? 10.0 : 42.0;
        double norm = sqrt(mean + 1e-9);
        int i = threadIdx.x / mside, j = threadIdx.x % mside;
        cx[threadIdx.x] = (float)((double)(-(mside - 1) + 2 * i) / norm);
        cy[threadIdx.x] = (float)((double)(-(mside - 1) + 2 * j) / norm);
    }
    if (threadIdx.x == 0) {
        uint32_t o0, o1;
        threefry2x32(0u, 42u, 0u, (uint32_t)m, o0, o1);
        skey[0] = o0; skey[1] = o1;
    }
    __syncthreads();
    uint32_t k0 = skey[0], k1 = skey[1];
    const int* idxrow = g_indices + b * NN;
    uint8_t* bitrow = g_bits + b * PADB;
    for (int s = threadIdx.x; s < n_sym; s += 256) {
        int p0 = s * bps, sym = 0;
        for (int j = 0; j < bps; j++) {
            int p = p0 + j, bit = 0;
            if (p < TOTB) bit = (idxrow[p / 10] >> (9 - p % 10)) & 1;
            sym = (sym << 1) | bit;
        }
        float tx0 = cx[sym], tx1 = cy[sym];
        uint32_t i0 = (uint32_t)(b * n_sym + s) * 2u;
        float rx0 = __fadd_rn(tx0, __fmul_rn(std_, gen_normal_part(k0, k1, i0)));
        float rx1 = __fadd_rn(tx1, __fmul_rn(std_, gen_normal_part(k0, k1, i0 + 1u)));
        float best = 3.402823466e+38f; int bi = 0;
        for (int k = 0; k < M; k++) {
            float dx = __fsub_rn(rx0, cx[k]), dy = __fsub_rn(rx1, cy[k]);
            float d = __fadd_rn(__fmul_rn(dx, dx), __fmul_rn(dy, dy));
            if (d < best) { best = d; bi = k; }
        }
        for (int j = 0; j < bps; j++)
            bitrow[p0 + j] = (uint8_t)((bi >> (bps - 1 - j)) & 1);
    }
}

// ---- K6: idx_hat + H_hat + vq_loss ----
__global__ void __launch_bounds__(256) final_kernel(const float* __restrict__ H,
                                                    const float* __restrict__ cb,
                                                    float* __restrict__ out) {
    __shared__ int sidx[16];
    int t = threadIdx.x;
    int row0 = blockIdx.x * 16;
    int b = row0 >> 10;
    int r = g_expert[b];
    if (t < 16) {
        int row = row0 + t;
        int n = row & (NN - 1);
        const uint8_t* bt = g_bits + b * PADB + n * 10;
        int v = 0;
        #pragma unroll
        for (int j = 0; j < 10; j++) v = (v << 1) | bt[j];
        if (v > NK - 1) v = NK - 1;
        sidx[t] = v;
        out[OFF_IDXHAT + row] = (float)v;
    }
    __syncthreads();
    #pragma unroll
    for (int it = 0; it < 4; it++) {
        int qid = it * 256 + t;
        int rl = qid >> 6, qq = qid & 63;
        size_t row = (size_t)row0 + rl;
        float4 h = reinterpret_cast<const float4*>(H)[row * 64 + qq];
        float4 c = reinterpret_cast<const float4*>(cb)[((size_t)r * 1024 + sidx[rl]) * 64 + qq];
        reinterpret_cast<float4*>(out + OFF_HHAT)[row * 64 + qq] =
            make_float4(__fadd_rn(h.x, __fsub_rn(c.x, h.x)), __fadd_rn(h.y, __fsub_rn(c.y, h.y)),
                        __fadd_rn(h.z, __fsub_rn(c.z, h.z)), __fadd_rn(h.w, __fsub_rn(c.w, h.w)));
    }
    if (blockIdx.x == 0 && t == 0) {
        double denom = (double)NB * (double)NN * (double)NCH * (double)NCH;
        out[OFF_VQ] = (float)(1.25 * g_sse / denom);
    }
}

// ---- launch ----
extern "C" void kernel_launch(void* const* d_in, const int* in_sizes, int n_in,
                              void* d_out, int out_size) {
    const float* H         = (const float*)d_in[0];
    const float* phi       = (const float*)d_in[1];
    const float* w0        = (const float*)d_in[2];
    const float* b0        = (const float*)d_in[3];
    const float* w1        = (const float*)d_in[4];
    const float* b1        = (const float*)d_in[5];
    const float* w2        = (const float*)d_in[6];
    const float* b2        = (const float*)d_in[7];
    const float* codebooks = (const float*)d_in[8];
    const float* noise_var = (const float*)d_in[9];
    float* out = (float*)d_out;

    cudaFuncSetAttribute(vqm_kernel, cudaFuncAttributeMaxDynamicSharedMemorySize, SM_TOT);

    prep_kernel<<<(NB * NN * NCH / 4 + NR * NK * NCH / 4 + 255) / 256, 256>>>(H, codebooks);
    mlp_kernel<<<NB, 128>>>(phi, w0, b0, w1, b1, w2, b2, noise_var, out);
    sq_kernel<<<(NB * NN + NR * NK + 7) / 8, 256>>>(H, codebooks);
    vqm_kernel<<<NB * NN / 128, 256, SM_TOT>>>();
    p2_kernel<<<NB * NN / 8, 256>>>(H, codebooks);
    zq_kernel<<<NB * NN / 16, 256>>>(H, codebooks, out);
    channel_kernel<<<NB, 256>>>();
    final_kernel<<<NB * NN / 16, 256>>>(H, codebooks, out);
}

// round 9
// speedup vs baseline: 1.8346x; 1.2511x over previous
#include <cuda_runtime.h>
#include <cuda_bf16.h>
#include <stdint.h>
#include <math.h>

#define NB 64
#define NN 1024
#define NCH 256
#define NR 4
#define NK 1024
#define TOTB 10240
#define PADB 10248
#define EPSF 0.25f
#define P2M  0.1f
#define CCAP 128
#define FMAXV 3.402823466e+38f

#define OFF_HHAT   0LL
#define OFF_ZQ     16777216LL
#define OFF_IND    33554432LL
#define OFF_IDXHAT 33619968LL
#define OFF_VQ     33685504LL
#define OFF_LOGITS 33685505LL
#define OFF_PROBS  33686273LL
#define OFF_MODE   33687041LL

__device__ int     g_expert[NB];
__device__ int     g_phy[NB];
__device__ float   g_std;
__device__ float   g_zsq[NB * NN];
__device__ float   g_cbsq[NR * NK];
__device__ int     g_indices[NB * NN];
__device__ uint8_t g_bits[NB * PADB];
__device__ double  g_sse;
__device__ __align__(16) __nv_bfloat16 g_Hb[NB * NN * NCH];
__device__ __align__(16) __nv_bfloat16 g_cbb[NR * NK * NCH];
__device__ int   g_cand[(size_t)NB * NN * CCAP];
__device__ float g_candd[(size_t)NB * NN * CCAP];
__device__ int   g_cc[NB * NN];

// ---- helpers ----
__device__ __forceinline__ uint32_t smem_to_u32(const void* p) {
    uint32_t a;
    asm("{ .reg .u64 t; cvta.to.shared.u64 t, %1; cvt.u32.u64 %0, t; }" : "=r"(a) : "l"(p));
    return a;
}
__device__ __forceinline__ void ldmx4(uint32_t* r, uint32_t addr) {
    asm volatile("ldmatrix.sync.aligned.m8n8.x4.shared.b16 {%0,%1,%2,%3}, [%4];"
        : "=r"(r[0]), "=r"(r[1]), "=r"(r[2]), "=r"(r[3]) : "r"(addr));
}
__device__ __forceinline__ void ldmx2(uint32_t* r, uint32_t addr) {
    asm volatile("ldmatrix.sync.aligned.m8n8.x2.shared.b16 {%0,%1}, [%2];"
        : "=r"(r[0]), "=r"(r[1]) : "r"(addr));
}
__device__ __forceinline__ void mma_bf16(float* c, const uint32_t* a, const uint32_t* b) {
    asm volatile("mma.sync.aligned.m16n8k16.row.col.f32.bf16.bf16.f32 "
        "{%0,%1,%2,%3}, {%4,%5,%6,%7}, {%8,%9}, {%0,%1,%2,%3};"
        : "+f"(c[0]), "+f"(c[1]), "+f"(c[2]), "+f"(c[3])
        : "r"(a[0]), "r"(a[1]), "r"(a[2]), "r"(a[3]), "r"(b[0]), "r"(b[1]));
}
__device__ __forceinline__ void cp16(uint32_t dst, const void* src) {
    asm volatile("cp.async.cg.shared.global [%0], [%1], 16;" :: "r"(dst), "l"(src));
}

// ---- threefry (JAX) ----
__device__ __forceinline__ uint32_t rotl32(uint32_t x, int r) { return (x << r) | (x >> (32 - r)); }
__device__ __forceinline__ void threefry2x32(uint32_t k0, uint32_t k1, uint32_t x0, uint32_t x1,
                                             uint32_t& o0, uint32_t& o1) {
    uint32_t k2 = k0 ^ k1 ^ 0x1BD11BDAu;
    x0 += k0; x1 += k1;
#define TF_R(a) x0 += x1; x1 = rotl32(x1, a); x1 ^= x0;
#define TF_G(a,b,c,d) TF_R(a) TF_R(b) TF_R(c) TF_R(d)
    TF_G(13, 15, 26, 6)  x0 += k1; x1 += k2 + 1u;
    TF_G(17, 29, 16, 24) x0 += k2; x1 += k0 + 2u;
    TF_G(13, 15, 26, 6)  x0 += k0; x1 += k1 + 3u;
    TF_G(17, 29, 16, 24) x0 += k1; x1 += k2 + 4u;
    TF_G(13, 15, 26, 6)  x0 += k2; x1 += k0 + 5u;
#undef TF_G
#undef TF_R
    o0 = x0; o1 = x1;
}
__device__ __forceinline__ float jax_normal_from_bits(uint32_t bits) {
    float u1 = __uint_as_float(0x3f800000u | (bits >> 9)) - 1.0f;
    const float lo = __uint_as_float(0xBF7FFFFFu);
    float u = __fadd_rn(__fmul_rn(u1, 2.0f), lo);
    u = fmaxf(u, lo);
    float w = -log1pf(-__fmul_rn(u, u));
    float p;
    if (w < 5.0f) {
        w = __fsub_rn(w, 2.5f);
        p = 2.81022636e-08f;
        p = __fmaf_rn(p, w, 3.43273939e-07f);
        p = __fmaf_rn(p, w, -3.5233877e-06f);
        p = __fmaf_rn(p, w, -4.39150654e-06f);
        p = __fmaf_rn(p, w, 0.00021858087f);
        p = __fmaf_rn(p, w, -0.00125372503f);
        p = __fmaf_rn(p, w, -0.00417768164f);
        p = __fmaf_rn(p, w, 0.246640727f);
        p = __fmaf_rn(p, w, 1.50140941f);
    } else {
        w = __fsub_rn(sqrtf(w), 3.0f);
        p = -0.000200214257f;
        p = __fmaf_rn(p, w, 0.000100950558f);
        p = __fmaf_rn(p, w, 0.00134934322f);
        p = __fmaf_rn(p, w, -0.00367342844f);
        p = __fmaf_rn(p, w, 0.00573950773f);
        p = __fmaf_rn(p, w, -0.0076224613f);
        p = __fmaf_rn(p, w, 0.00943887047f);
        p = __fmaf_rn(p, w, 1.00167406f);
        p = __fmaf_rn(p, w, 2.83297682f);
    }
    return __fmul_rn(__uint_as_float(0x3FB504F3u), __fmul_rn(p, u));
}
__device__ __forceinline__ float gen_normal_part(uint32_t k0, uint32_t k1, uint32_t i) {
    uint32_t o0, o1;
    threefry2x32(k0, k1, 0u, i, o0, o1);
    return jax_normal_from_bits(o0 ^ o1);
}

// ---- K0: bf16 convert ----
__global__ void __launch_bounds__(256) prep_kernel(const float* __restrict__ H,
                                                   const float* __restrict__ cb) {
    int i = blockIdx.x * 256 + threadIdx.x;
    const int NH4 = NB * NN * NCH / 4, NC4 = NR * NK * NCH / 4;
    if (i < NH4) {
        float4 v = reinterpret_cast<const float4*>(H)[i];
        __nv_bfloat162 p0 = __floats2bfloat162_rn(v.x, v.y), p1 = __floats2bfloat162_rn(v.z, v.w);
        reinterpret_cast<uint2*>(g_Hb)[i] = make_uint2(*(uint32_t*)&p0, *(uint32_t*)&p1);
    } else if (i - NH4 < NC4) {
        int j = i - NH4;
        float4 v = reinterpret_cast<const float4*>(cb)[j];
        __nv_bfloat162 p0 = __floats2bfloat162_rn(v.x, v.y), p1 = __floats2bfloat162_rn(v.z, v.w);
        reinterpret_cast<uint2*>(g_cbb)[j] = make_uint2(*(uint32_t*)&p0, *(uint32_t*)&p1);
    }
}

// ---- K1: router MLP ----
__global__ void __launch_bounds__(128) mlp_kernel(
    const float* __restrict__ phi, const float* __restrict__ w0, const float* __restrict__ b0,
    const float* __restrict__ w1, const float* __restrict__ b1, const float* __restrict__ w2,
    const float* __restrict__ b2, const float* __restrict__ noise_var, float* __restrict__ out) {
    __shared__ float sphi[512], sh[128], sh2[128], sl[12];
    int b = blockIdx.x, t = threadIdx.x;
    if (b == 0 && t == 0) g_sse = 0.0;
    for (int d = t; d < 512; d += 128) sphi[d] = phi[b * 512 + d];
    __syncthreads();
    float a = 0.f;
    #pragma unroll 8
    for (int d = 0; d < 512; d++) a = __fmaf_rn(sphi[d], w0[d * 128 + t], a);
    sh[t] = fmaxf(__fadd_rn(a, b0[t]), 0.f);
    __syncthreads();
    float a2 = 0.f;
    #pragma unroll 8
    for (int i = 0; i < 128; i++) a2 = __fmaf_rn(sh[i], w1[i * 128 + t], a2);
    sh2[t] = fmaxf(__fadd_rn(a2, b1[t]), 0.f);
    __syncthreads();
    if (t < 12) {
        float l = 0.f;
        for (int i = 0; i < 128; i++) l = __fmaf_rn(sh2[i], w2[i * 12 + t], l);
        l = __fadd_rn(l, b2[t]);
        sl[t] = l;
        out[OFF_LOGITS + b * 12 + t] = l;
    }
    __syncthreads();
    if (t == 0) {
        float mx = sl[0]; int mi = 0;
        for (int j = 1; j < 12; j++) if (sl[j] > mx) { mx = sl[j]; mi = j; }
        float e[12], s = 0.f;
        for (int j = 0; j < 12; j++) { e[j] = expf(__fsub_rn(sl[j], mx)); s = __fadd_rn(s, e[j]); }
        for (int j = 0; j < 12; j++) out[OFF_PROBS + b * 12 + j] = __fdiv_rn(e[j], s);
        out[OFF_MODE + b] = (float)mi;
        g_expert[b] = mi / 3;
        g_phy[b] = mi % 3;
        if (b == 0) g_std = sqrtf(fmaxf(noise_var[0], 0.f));
    }
}

// ---- K2: row squared norms (UNCHANGED ordering — validated) ----
__global__ void __launch_bounds__(256) sq_kernel(const float* __restrict__ H,
                                                 const float* __restrict__ cb) {
    int warp = (blockIdx.x * blockDim.x + threadIdx.x) >> 5;
    int lane = threadIdx.x & 31;
    const int TOT = NB * NN + NR * NK;
    if (warp >= TOT) return;
    const float* src = (warp < NB * NN) ? (H + (size_t)warp * NCH) : (cb + (size_t)(warp - NB * NN) * NCH);
    double s = 0.0;
    #pragma unroll
    for (int c = lane; c < NCH; c += 32) { float v = src[c]; s += (double)__fmul_rn(v, v); }
    #pragma unroll
    for (int o = 16; o; o >>= 1) s += __shfl_down_sync(0xffffffffu, s, o);
    if (lane == 0) { if (warp < NB * NN) g_zsq[warp] = (float)s; else g_cbsq[warp - NB * NN] = (float)s; }
}

// ---- K3: bf16 mma GEMM, A persistent, B double-buffered cp.async, register epilogue ----
#define PADK 264
#define BELEM 33792
#define S2_ZSQ 0
#define S2_CBSQ 512
#define S2_MIN 4608
#define S2_CNT 5120
#define S2_RMIN 5632
#define S2_A 6656
#define S2_B 74240
#define S2_TOT 209408

__global__ void __launch_bounds__(256, 1) vqm_kernel() {
    extern __shared__ char smem[];
    float* zsq_s = (float*)(smem + S2_ZSQ);
    float* cbsq_s = (float*)(smem + S2_CBSQ);
    float* minv_s = (float*)(smem + S2_MIN);
    int*   cnt_s = (int*)(smem + S2_CNT);
    float* rmin_s = (float*)(smem + S2_RMIN);

    int tid = threadIdx.x, wid = tid >> 5, lane = tid & 31;
    int row0 = blockIdx.x * 128;
    int r = g_expert[row0 >> 10];
    if (tid < 128) { zsq_s[tid] = g_zsq[row0 + tid]; minv_s[tid] = FMAXV; cnt_s[tid] = 0; }
    for (int j = tid; j < 1024; j += 256) cbsq_s[j] = g_cbsq[r * 1024 + j];

    uint32_t aBase = smem_to_u32(smem + S2_A);
    uint32_t bBase = smem_to_u32(smem + S2_B);

    #pragma unroll
    for (int it = 0; it < 16; it++) {
        int u = it * 256 + tid; int rr = u >> 5, kk = (u & 31) * 8;
        cp16(aBase + (uint32_t)(rr * PADK + kk) * 2, g_Hb + (size_t)(row0 + rr) * 256 + kk);
    }
    #pragma unroll
    for (int it = 0; it < 16; it++) {
        int u = it * 256 + tid; int rr = u >> 5, kk = (u & 31) * 8;
        cp16(bBase + (uint32_t)(rr * PADK + kk) * 2, g_cbb + (size_t)(r * 1024 + rr) * 256 + kk);
    }
    asm volatile("cp.async.commit_group;");

    int warp_m = wid & 3, warp_n = wid >> 2;
    int q = lane >> 2, s4 = lane & 3;

    for (int ch = 0; ch < 8; ch++) {
        int buf = ch & 1;
        if (ch < 7) {
            uint32_t bb = bBase + (uint32_t)(1 - buf) * BELEM * 2;
            #pragma unroll
            for (int it = 0; it < 16; it++) {
                int u = it * 256 + tid; int rr = u >> 5, kk = (u & 31) * 8;
                cp16(bb + (uint32_t)(rr * PADK + kk) * 2,
                     g_cbb + (size_t)(r * 1024 + (ch + 1) * 128 + rr) * 256 + kk);
            }
            asm volatile("cp.async.commit_group;");
            asm volatile("cp.async.wait_group 1;");
        } else {
            asm volatile("cp.async.wait_group 0;");
        }
        __syncthreads();

        float acc[2][8][4];
        #pragma unroll
        for (int mf = 0; mf < 2; mf++)
            #pragma unroll
            for (int nf = 0; nf < 8; nf++)
                #pragma unroll
                for (int v = 0; v < 4; v++) acc[mf][nf][v] = 0.f;

        uint32_t bcur = bBase + (uint32_t)buf * BELEM * 2;
        #pragma unroll
        for (int k16 = 0; k16 < 16; k16++) {
            int kcol = k16 * 16;
            uint32_t af[2][4], bfr[8][2];
            #pragma unroll
            for (int mf = 0; mf < 2; mf++) {
                int arow = warp_m * 32 + mf * 16 + (lane & 7) + ((lane >> 3) & 1) * 8;
                int acol = kcol + (lane >> 4) * 8;
                ldmx4(af[mf], aBase + (uint32_t)(arow * PADK + acol) * 2);
            }
            #pragma unroll
            for (int nf = 0; nf < 8; nf++) {
                int l = lane & 15;
                int brow = warp_n * 64 + nf * 8 + (l & 7);
                int bcol = kcol + ((l >> 3) & 1) * 8;
                ldmx2(bfr[nf], bcur + (uint32_t)(brow * PADK + bcol) * 2);
            }
            #pragma unroll
            for (int mf = 0; mf < 2; mf++)
                #pragma unroll
                for (int nf = 0; nf < 8; nf++)
                    mma_bf16(acc[mf][nf], af[mf], bfr[nf]);
        }

        // epilogue: per-row mins from registers
        #pragma unroll
        for (int mf = 0; mf < 2; mf++) {
            int r1 = warp_m * 32 + mf * 16 + q;
            float z1 = zsq_s[r1], z2 = zsq_s[r1 + 8];
            float m1 = FMAXV, m2 = FMAXV;
            #pragma unroll
            for (int nf = 0; nf < 8; nf++) {
                #pragma unroll
                for (int v = 0; v < 2; v++) {
                    int col = warp_n * 64 + nf * 8 + s4 * 2 + v;
                    float cq = cbsq_s[ch * 128 + col];
                    m1 = fminf(m1, __fmaf_rn(-2.f, acc[mf][nf][v], __fadd_rn(z1, cq)));
                    m2 = fminf(m2, __fmaf_rn(-2.f, acc[mf][nf][v + 2], __fadd_rn(z2, cq)));
                }
            }
            m1 = fminf(m1, __shfl_xor_sync(0xffffffffu, m1, 1));
            m1 = fminf(m1, __shfl_xor_sync(0xffffffffu, m1, 2));
            m2 = fminf(m2, __shfl_xor_sync(0xffffffffu, m2, 1));
            m2 = fminf(m2, __shfl_xor_sync(0xffffffffu, m2, 2));
            if (s4 == 0) { rmin_s[r1 * 2 + warp_n] = m1; rmin_s[(r1 + 8) * 2 + warp_n] = m2; }
        }
        __syncthreads();
        if (tid < 128) minv_s[tid] = fminf(minv_s[tid], fminf(rmin_s[tid * 2], rmin_s[tid * 2 + 1]));
        __syncthreads();
        // collect candidates
        #pragma unroll
        for (int mf = 0; mf < 2; mf++) {
            int r1 = warp_m * 32 + mf * 16 + q;
            float z1 = zsq_s[r1], z2 = zsq_s[r1 + 8];
            float t1 = minv_s[r1] + EPSF, t2 = minv_s[r1 + 8] + EPSF;
            #pragma unroll
            for (int nf = 0; nf < 8; nf++) {
                #pragma unroll
                for (int v = 0; v < 2; v++) {
                    int col = warp_n * 64 + nf * 8 + s4 * 2 + v;
                    float cq = cbsq_s[ch * 128 + col];
                    float d1 = __fmaf_rn(-2.f, acc[mf][nf][v], __fadd_rn(z1, cq));
                    if (d1 <= t1) {
                        int pos = atomicAdd(&cnt_s[r1], 1);
                        if (pos < CCAP) {
                            g_cand[(size_t)(row0 + r1) * CCAP + pos] = ch * 128 + col;
                            g_candd[(size_t)(row0 + r1) * CCAP + pos] = d1;
                        }
                    }
                    float d2 = __fmaf_rn(-2.f, acc[mf][nf][v + 2], __fadd_rn(z2, cq));
                    if (d2 <= t2) {
                        int pos = atomicAdd(&cnt_s[r1 + 8], 1);
                        if (pos < CCAP) {
                            g_cand[(size_t)(row0 + r1 + 8) * CCAP + pos] = ch * 128 + col;
                            g_candd[(size_t)(row0 + r1 + 8) * CCAP + pos] = d2;
                        }
                    }
                }
            }
        }
        __syncthreads();
    }
    if (tid < 128) g_cc[row0 + tid] = cnt_s[tid];
}

// ---- K3b: re-rank — d̃ prefilter + lane-parallel exact sequential chains ----
__device__ __forceinline__ float seq_d(const float* __restrict__ z, const float* __restrict__ cr,
                                       float zsqv, float cbsqj) {
    float acc = 0.f;
    #pragma unroll 8
    for (int k = 0; k < 256; k++) acc = __fmaf_rn(z[k], cr[k], acc);
    return __fmaf_rn(-2.0f, acc, __fadd_rn(zsqv, cbsqj));
}
__global__ void __launch_bounds__(256) p2_kernel(const float* __restrict__ H,
                                                 const float* __restrict__ cb) {
    int wid = threadIdx.x >> 5, lane = threadIdx.x & 31;
    int row = blockIdx.x * 8 + wid;
    int r = g_expert[row >> 10];
    const float* z = H + (size_t)row * 256;
    const float* cbase = cb + (size_t)r * 1024 * 256;
    const float* cbsq = g_cbsq + r * 1024;
    float zsqv = g_zsq[row];
    int c = g_cc[row];
    float best = FMAXV; int bestj = 0x7fffffff;
    if (c <= CCAP) {
        float dmin = FMAXV;
        for (int i0 = 0; i0 < c; i0 += 32) {
            float dv = (i0 + lane < c) ? g_candd[(size_t)row * CCAP + i0 + lane] : FMAXV;
            #pragma unroll
            for (int o = 16; o; o >>= 1) dv = fminf(dv, __shfl_xor_sync(0xffffffffu, dv, o));
            dmin = fminf(dmin, dv);
        }
        float thr = dmin + P2M;
        for (int i0 = 0; i0 < c; i0 += 32) {
            int idx = i0 + lane;
            float dv = (idx < c) ? g_candd[(size_t)row * CCAP + idx] : FMAXV;
            int j = (idx < c) ? g_cand[(size_t)row * CCAP + idx] : 0x7fffffff;
            float ds = FMAXV;
            if (dv <= thr) ds = seq_d(z, cbase + (size_t)j * 256, zsqv, cbsq[j]);
            else j = 0x7fffffff;
            #pragma unroll
            for (int o = 16; o; o >>= 1) {
                float od = __shfl_xor_sync(0xffffffffu, ds, o);
                int oj = __shfl_xor_sync(0xffffffffu, j, o);
                if (od < ds || (od == ds && oj < j)) { ds = od; j = oj; }
            }
            if (ds < best || (ds == best && j < bestj)) { best = ds; bestj = j; }
        }
    } else {
        for (int j0 = 0; j0 < 1024; j0 += 32) {
            int j = j0 + lane;
            float ds = seq_d(z, cbase + (size_t)j * 256, zsqv, cbsq[j]);
            #pragma unroll
            for (int o = 16; o; o >>= 1) {
                float od = __shfl_xor_sync(0xffffffffu, ds, o);
                int oj = __shfl_xor_sync(0xffffffffu, j, o);
                if (od < ds || (od == ds && oj < j)) { ds = od; j = oj; }
            }
            if (ds < best || (ds == best && j < bestj)) { best = ds; bestj = j; }
        }
    }
    if (lane == 0) g_indices[row] = bestj;
}

// ---- K4: z_q + SSE + indices ----
__global__ void __launch_bounds__(256) zq_kernel(const float* __restrict__ H,
                                                 const float* __restrict__ cb,
                                                 float* __restrict__ out) {
    __shared__ int sidx[16];
    __shared__ double red[256];
    int t = threadIdx.x;
    int row0 = blockIdx.x * 16;
    int r = g_expert[row0 >> 10];
    if (t < 16) {
        int row = row0 + t;
        int v = g_indices[row];
        sidx[t] = v;
        out[OFF_IND + row] = (float)v;
    }
    __syncthreads();
    double acc = 0.0;
    #pragma unroll
    for (int it = 0; it < 4; it++) {
        int qid = it * 256 + t;
        int rl = qid >> 6, qq = qid & 63;
        size_t row = (size_t)row0 + rl;
        float4 h = reinterpret_cast<const float4*>(H)[row * 64 + qq];
        float4 qv = reinterpret_cast<const float4*>(cb)[((size_t)r * 1024 + sidx[rl]) * 64 + qq];
        float dx = __fsub_rn(qv.x, h.x), dy = __fsub_rn(qv.y, h.y);
        float dz = __fsub_rn(qv.z, h.z), dw = __fsub_rn(qv.w, h.w);
        reinterpret_cast<float4*>(out + OFF_ZQ)[row * 64 + qq] =
            make_float4(__fadd_rn(h.x, dx), __fadd_rn(h.y, dy), __fadd_rn(h.z, dz), __fadd_rn(h.w, dw));
        acc += (double)__fmul_rn(dx, dx) + (double)__fmul_rn(dy, dy)
             + (double)__fmul_rn(dz, dz) + (double)__fmul_rn(dw, dw);
    }
    red[t] = acc;
    __syncthreads();
    for (int s = 128; s; s >>= 1) { if (t < s) red[t] += red[t + s]; __syncthreads(); }
    if (t == 0) atomicAdd(&g_sse, red[0]);
}

// ---- K5: QAM channel ----
__global__ void __launch_bounds__(256) channel_kernel() {
    int b = blockIdx.x;
    int m = g_phy[b];
    int bps = (m == 0) ? 2 : (m == 1) ? 4 : 6;
    int n_sym = PADB / bps;
    int mside = (m == 0) ? 2 : (m == 1) ? 4 : 8;
    int M = mside * mside;
    float std_ = g_std;
    __shared__ float cx[64], cy[64];
    __shared__ uint32_t skey[2];
    if (threadIdx.x < M) {
        double mean = (m == 0) ? 2.0 : (m == 1) ? 10.0 : 42.0;
        double norm = sqrt(mean + 1e-9);
        int i = threadIdx.x / mside, j = threadIdx.x % mside;
        cx[threadIdx.x] = (float)((double)(-(mside - 1) + 2 * i) / norm);
        cy[threadIdx.x] = (float)((double)(-(mside - 1) + 2 * j) / norm);
    }
    if (threadIdx.x == 0) {
        uint32_t o0, o1;
        threefry2x32(0u, 42u, 0u, (uint32_t)m, o0, o1);
        skey[0] = o0; skey[1] = o1;
    }
    __syncthreads();
    uint32_t k0 = skey[0], k1 = skey[1];
    const int* idxrow = g_indices + b * NN;
    uint8_t* bitrow = g_bits + b * PADB;
    for (int s = threadIdx.x; s < n_sym; s += 256) {
        int p0 = s * bps, sym = 0;
        for (int j = 0; j < bps; j++) {
            int p = p0 + j, bit = 0;
            if (p < TOTB) bit = (idxrow[p / 10] >> (9 - p % 10)) & 1;
            sym = (sym << 1) | bit;
        }
        float tx0 = cx[sym], tx1 = cy[sym];
        uint32_t i0 = (uint32_t)(b * n_sym + s) * 2u;
        float rx0 = __fadd_rn(tx0, __fmul_rn(std_, gen_normal_part(k0, k1, i0)));
        float rx1 = __fadd_rn(tx1, __fmul_rn(std_, gen_normal_part(k0, k1, i0 + 1u)));
        float best = FMAXV; int bi = 0;
        for (int k = 0; k < M; k++) {
            float dx = __fsub_rn(rx0, cx[k]), dy = __fsub_rn(rx1, cy[k]);
            float d = __fadd_rn(__fmul_rn(dx, dx), __fmul_rn(dy, dy));
            if (d < best) { best = d; bi = k; }
        }
        for (int j = 0; j < bps; j++)
            bitrow[p0 + j] = (uint8_t)((bi >> (bps - 1 - j)) & 1);
    }
}

// ---- K6: idx_hat + H_hat + vq_loss ----
__global__ void __launch_bounds__(256) final_kernel(const float* __restrict__ H,
                                                    const float* __restrict__ cb,
                                                    float* __restrict__ out) {
    __shared__ int sidx[16];
    int t = threadIdx.x;
    int row0 = blockIdx.x * 16;
    int b = row0 >> 10;
    int r = g_expert[b];
    if (t < 16) {
        int row = row0 + t;
        int n = row & (NN - 1);
        const uint8_t* bt = g_bits + b * PADB + n * 10;
        int v = 0;
        #pragma unroll
        for (int j = 0; j < 10; j++) v = (v << 1) | bt[j];
        if (v > NK - 1) v = NK - 1;
        sidx[t] = v;
        out[OFF_IDXHAT + row] = (float)v;
    }
    __syncthreads();
    #pragma unroll
    for (int it = 0; it < 4; it++) {
        int qid = it * 256 + t;
        int rl = qid >> 6, qq = qid & 63;
        size_t row = (size_t)row0 + rl;
        float4 h = reinterpret_cast<const float4*>(H)[row * 64 + qq];
        float4 c = reinterpret_cast<const float4*>(cb)[((size_t)r * 1024 + sidx[rl]) * 64 + qq];
        reinterpret_cast<float4*>(out + OFF_HHAT)[row * 64 + qq] =
            make_float4(__fadd_rn(h.x, __fsub_rn(c.x, h.x)), __fadd_rn(h.y, __fsub_rn(c.y, h.y)),
                        __fadd_rn(h.z, __fsub_rn(c.z, h.z)), __fadd_rn(h.w, __fsub_rn(c.w, h.w)));
    }
    if (blockIdx.x == 0 && t == 0) {
        double denom = (double)NB * (double)NN * (double)NCH * (double)NCH;
        out[OFF_VQ] = (float)(1.25 * g_sse / denom);
    }
}

// ---- launch ----
extern "C" void kernel_launch(void* const* d_in, const int* in_sizes, int n_in,
                              void* d_out, int out_size) {
    const float* H         = (const float*)d_in[0];
    const float* phi       = (const float*)d_in[1];
    const float* w0        = (const float*)d_in[2];
    const float* b0        = (const float*)d_in[3];
    const float* w1        = (const float*)d_in[4];
    const float* b1        = (const float*)d_in[5];
    const float* w2        = (const float*)d_in[6];
    const float* b2        = (const float*)d_in[7];
    const float* codebooks = (const float*)d_in[8];
    const float* noise_var = (const float*)d_in[9];
    float* out = (float*)d_out;

    cudaFuncSetAttribute(vqm_kernel, cudaFuncAttributeMaxDynamicSharedMemorySize, S2_TOT);

    prep_kernel<<<(NB * NN * NCH / 4 + NR * NK * NCH / 4 + 255) / 256, 256>>>(H, codebooks);
    mlp_kernel<<<NB, 128>>>(phi, w0, b0, w1, b1, w2, b2, noise_var, out);
    sq_kernel<<<(NB * NN + NR * NK + 7) / 8, 256>>>(H, codebooks);
    vqm_kernel<<<NB * NN / 128, 256, S2_TOT>>>();
    p2_kernel<<<NB * NN / 8, 256>>>(H, codebooks);
    zq_kernel<<<NB * NN / 16, 256>>>(H, codebooks, out);
    channel_kernel<<<NB, 256>>>();
    final_kernel<<<NB * NN / 16, 256>>>(H, codebooks, out);
}

// round 10
// speedup vs baseline: 1.9897x; 1.0845x over previous
#include <cuda_runtime.h>
#include <cuda_bf16.h>
#include <stdint.h>
#include <math.h>

#define NB 64
#define NN 1024
#define NCH 256
#define NR 4
#define NK 1024
#define TOTB 10240
#define PADB 10248
#define EPSF 0.25f
#define P2M  0.1f
#define CCAP 128
#define FMAXV 3.402823466e+38f

#define OFF_HHAT   0LL
#define OFF_ZQ     16777216LL
#define OFF_IND    33554432LL
#define OFF_IDXHAT 33619968LL
#define OFF_VQ     33685504LL
#define OFF_LOGITS 33685505LL
#define OFF_PROBS  33686273LL
#define OFF_MODE   33687041LL

__device__ int     g_expert[NB];
__device__ int     g_phy[NB];
__device__ float   g_std;
__device__ float   g_zsq[NB * NN];
__device__ float   g_cbsq[NR * NK];
__device__ int     g_indices[NB * NN];
__device__ uint8_t g_bits[NB * PADB];
__device__ double  g_sse;
__device__ __align__(16) __nv_bfloat16 g_Hb[NB * NN * NCH];
__device__ __align__(16) __nv_bfloat16 g_cbb[NR * NK * NCH];
__device__ int   g_cand[(size_t)NB * NN * CCAP];
__device__ float g_candd[(size_t)NB * NN * CCAP];
__device__ int   g_cc[NB * NN];

// ---- helpers ----
__device__ __forceinline__ uint32_t smem_to_u32(const void* p) {
    uint32_t a;
    asm("{ .reg .u64 t; cvta.to.shared.u64 t, %1; cvt.u32.u64 %0, t; }" : "=r"(a) : "l"(p));
    return a;
}
__device__ __forceinline__ void ldmx4(uint32_t* r, uint32_t addr) {
    asm volatile("ldmatrix.sync.aligned.m8n8.x4.shared.b16 {%0,%1,%2,%3}, [%4];"
        : "=r"(r[0]), "=r"(r[1]), "=r"(r[2]), "=r"(r[3]) : "r"(addr));
}
__device__ __forceinline__ void ldmx2(uint32_t* r, uint32_t addr) {
    asm volatile("ldmatrix.sync.aligned.m8n8.x2.shared.b16 {%0,%1}, [%2];"
        : "=r"(r[0]), "=r"(r[1]) : "r"(addr));
}
__device__ __forceinline__ void mma_bf16(float* c, const uint32_t* a, const uint32_t* b) {
    asm volatile("mma.sync.aligned.m16n8k16.row.col.f32.bf16.bf16.f32 "
        "{%0,%1,%2,%3}, {%4,%5,%6,%7}, {%8,%9}, {%0,%1,%2,%3};"
        : "+f"(c[0]), "+f"(c[1]), "+f"(c[2]), "+f"(c[3])
        : "r"(a[0]), "r"(a[1]), "r"(a[2]), "r"(a[3]), "r"(b[0]), "r"(b[1]));
}
__device__ __forceinline__ void cp16(uint32_t dst, const void* src) {
    asm volatile("cp.async.cg.shared.global [%0], [%1], 16;" :: "r"(dst), "l"(src));
}

// ---- threefry (JAX) ----
__device__ __forceinline__ uint32_t rotl32(uint32_t x, int r) { return (x << r) | (x >> (32 - r)); }
__device__ __forceinline__ void threefry2x32(uint32_t k0, uint32_t k1, uint32_t x0, uint32_t x1,
                                             uint32_t& o0, uint32_t& o1) {
    uint32_t k2 = k0 ^ k1 ^ 0x1BD11BDAu;
    x0 += k0; x1 += k1;
#define TF_R(a) x0 += x1; x1 = rotl32(x1, a); x1 ^= x0;
#define TF_G(a,b,c,d) TF_R(a) TF_R(b) TF_R(c) TF_R(d)
    TF_G(13, 15, 26, 6)  x0 += k1; x1 += k2 + 1u;
    TF_G(17, 29, 16, 24) x0 += k2; x1 += k0 + 2u;
    TF_G(13, 15, 26, 6)  x0 += k0; x1 += k1 + 3u;
    TF_G(17, 29, 16, 24) x0 += k1; x1 += k2 + 4u;
    TF_G(13, 15, 26, 6)  x0 += k2; x1 += k0 + 5u;
#undef TF_G
#undef TF_R
    o0 = x0; o1 = x1;
}
__device__ __forceinline__ float jax_normal_from_bits(uint32_t bits) {
    float u1 = __uint_as_float(0x3f800000u | (bits >> 9)) - 1.0f;
    const float lo = __uint_as_float(0xBF7FFFFFu);
    float u = __fadd_rn(__fmul_rn(u1, 2.0f), lo);
    u = fmaxf(u, lo);
    float w = -log1pf(-__fmul_rn(u, u));
    float p;
    if (w < 5.0f) {
        w = __fsub_rn(w, 2.5f);
        p = 2.81022636e-08f;
        p = __fmaf_rn(p, w, 3.43273939e-07f);
        p = __fmaf_rn(p, w, -3.5233877e-06f);
        p = __fmaf_rn(p, w, -4.39150654e-06f);
        p = __fmaf_rn(p, w, 0.00021858087f);
        p = __fmaf_rn(p, w, -0.00125372503f);
        p = __fmaf_rn(p, w, -0.00417768164f);
        p = __fmaf_rn(p, w, 0.246640727f);
        p = __fmaf_rn(p, w, 1.50140941f);
    } else {
        w = __fsub_rn(sqrtf(w), 3.0f);
        p = -0.000200214257f;
        p = __fmaf_rn(p, w, 0.000100950558f);
        p = __fmaf_rn(p, w, 0.00134934322f);
        p = __fmaf_rn(p, w, -0.00367342844f);
        p = __fmaf_rn(p, w, 0.00573950773f);
        p = __fmaf_rn(p, w, -0.0076224613f);
        p = __fmaf_rn(p, w, 0.00943887047f);
        p = __fmaf_rn(p, w, 1.00167406f);
        p = __fmaf_rn(p, w, 2.83297682f);
    }
    return __fmul_rn(__uint_as_float(0x3FB504F3u), __fmul_rn(p, u));
}
__device__ __forceinline__ float gen_normal_part(uint32_t k0, uint32_t k1, uint32_t i) {
    uint32_t o0, o1;
    threefry2x32(k0, k1, 0u, i, o0, o1);
    return jax_normal_from_bits(o0 ^ o1);
}

// ---- K0: bf16 convert ----
__global__ void __launch_bounds__(256) prep_kernel(const float* __restrict__ H,
                                                   const float* __restrict__ cb) {
    int i = blockIdx.x * 256 + threadIdx.x;
    const int NH4 = NB * NN * NCH / 4, NC4 = NR * NK * NCH / 4;
    if (i < NH4) {
        float4 v = reinterpret_cast<const float4*>(H)[i];
        __nv_bfloat162 p0 = __floats2bfloat162_rn(v.x, v.y), p1 = __floats2bfloat162_rn(v.z, v.w);
        reinterpret_cast<uint2*>(g_Hb)[i] = make_uint2(*(uint32_t*)&p0, *(uint32_t*)&p1);
    } else if (i - NH4 < NC4) {
        int j = i - NH4;
        float4 v = reinterpret_cast<const float4*>(cb)[j];
        __nv_bfloat162 p0 = __floats2bfloat162_rn(v.x, v.y), p1 = __floats2bfloat162_rn(v.z, v.w);
        reinterpret_cast<uint2*>(g_cbb)[j] = make_uint2(*(uint32_t*)&p0, *(uint32_t*)&p1);
    }
}

// ---- K1: router MLP ----
__global__ void __launch_bounds__(128) mlp_kernel(
    const float* __restrict__ phi, const float* __restrict__ w0, const float* __restrict__ b0,
    const float* __restrict__ w1, const float* __restrict__ b1, const float* __restrict__ w2,
    const float* __restrict__ b2, const float* __restrict__ noise_var, float* __restrict__ out) {
    __shared__ float sphi[512], sh[128], sh2[128], sl[12];
    int b = blockIdx.x, t = threadIdx.x;
    if (b == 0 && t == 0) g_sse = 0.0;
    for (int d = t; d < 512; d += 128) sphi[d] = phi[b * 512 + d];
    __syncthreads();
    float a = 0.f;
    #pragma unroll 8
    for (int d = 0; d < 512; d++) a = __fmaf_rn(sphi[d], w0[d * 128 + t], a);
    sh[t] = fmaxf(__fadd_rn(a, b0[t]), 0.f);
    __syncthreads();
    float a2 = 0.f;
    #pragma unroll 8
    for (int i = 0; i < 128; i++) a2 = __fmaf_rn(sh[i], w1[i * 128 + t], a2);
    sh2[t] = fmaxf(__fadd_rn(a2, b1[t]), 0.f);
    __syncthreads();
    if (t < 12) {
        float l = 0.f;
        for (int i = 0; i < 128; i++) l = __fmaf_rn(sh2[i], w2[i * 12 + t], l);
        l = __fadd_rn(l, b2[t]);
        sl[t] = l;
        out[OFF_LOGITS + b * 12 + t] = l;
    }
    __syncthreads();
    if (t == 0) {
        float mx = sl[0]; int mi = 0;
        for (int j = 1; j < 12; j++) if (sl[j] > mx) { mx = sl[j]; mi = j; }
        float e[12], s = 0.f;
        for (int j = 0; j < 12; j++) { e[j] = expf(__fsub_rn(sl[j], mx)); s = __fadd_rn(s, e[j]); }
        for (int j = 0; j < 12; j++) out[OFF_PROBS + b * 12 + j] = __fdiv_rn(e[j], s);
        out[OFF_MODE + b] = (float)mi;
        g_expert[b] = mi / 3;
        g_phy[b] = mi % 3;
        if (b == 0) g_std = sqrtf(fmaxf(noise_var[0], 0.f));
    }
}

// ---- K2: row squared norms (ordering validated — do not touch) ----
__global__ void __launch_bounds__(256) sq_kernel(const float* __restrict__ H,
                                                 const float* __restrict__ cb) {
    int warp = (blockIdx.x * blockDim.x + threadIdx.x) >> 5;
    int lane = threadIdx.x & 31;
    const int TOT = NB * NN + NR * NK;
    if (warp >= TOT) return;
    const float* src = (warp < NB * NN) ? (H + (size_t)warp * NCH) : (cb + (size_t)(warp - NB * NN) * NCH);
    double s = 0.0;
    #pragma unroll
    for (int c = lane; c < NCH; c += 32) { float v = src[c]; s += (double)__fmul_rn(v, v); }
    #pragma unroll
    for (int o = 16; o; o >>= 1) s += __shfl_down_sync(0xffffffffu, s, o);
    if (lane == 0) { if (warp < NB * NN) g_zsq[warp] = (float)s; else g_cbsq[warp - NB * NN] = (float)s; }
}

// ---- K3: A-in-register bf16 mma, 32-col B chunks double-buffered, sync-free epilogue ----
#define PADK 264
#define BBUF 16896
#define S3_CBSQ 0
#define S3_CNT 4096
#define S3_B 4608
#define S3_TOT 38400

__global__ void __launch_bounds__(256, 2) vqm_kernel() {
    extern __shared__ char smem[];
    float* cbsq_s = (float*)(smem + S3_CBSQ);
    int* cnt_s = (int*)(smem + S3_CNT);
    uint32_t bBase = smem_to_u32(smem + S3_B);

    int tid = threadIdx.x, wid = tid >> 5, lane = tid & 31;
    int row0 = blockIdx.x * 128;
    int r = g_expert[row0 >> 10];
    for (int j = tid; j < 1024; j += 256) cbsq_s[j] = g_cbsq[r * 1024 + j];
    if (tid < 128) cnt_s[tid] = 0;

    // ---- load A fragments into registers (each warp owns 16 rows) ----
    uint32_t afrag[64];
    int arow_in = (lane & 7) + ((lane >> 3) & 1) * 8;
    int acolsel = (lane >> 4) * 8;
    // half 0: rows 0..63
    #pragma unroll
    for (int it = 0; it < 8; it++) {
        int u = it * 256 + tid; int rr = u >> 5, kk = (u & 31) * 8;
        cp16(bBase + (uint32_t)(rr * PADK + kk) * 2, g_Hb + (size_t)(row0 + rr) * 256 + kk);
    }
    asm volatile("cp.async.commit_group;");
    asm volatile("cp.async.wait_group 0;");
    __syncthreads();
    if (wid < 4) {
        int br = wid * 16 + arow_in;
        #pragma unroll
        for (int k16 = 0; k16 < 16; k16++)
            ldmx4(&afrag[k16 * 4], bBase + (uint32_t)(br * PADK + k16 * 16 + acolsel) * 2);
    }
    __syncthreads();
    // half 1: rows 64..127
    #pragma unroll
    for (int it = 0; it < 8; it++) {
        int u = it * 256 + tid; int rr = u >> 5, kk = (u & 31) * 8;
        cp16(bBase + (uint32_t)(rr * PADK + kk) * 2, g_Hb + (size_t)(row0 + 64 + rr) * 256 + kk);
    }
    asm volatile("cp.async.commit_group;");
    asm volatile("cp.async.wait_group 0;");
    __syncthreads();
    if (wid >= 4) {
        int br = (wid - 4) * 16 + arow_in;
        #pragma unroll
        for (int k16 = 0; k16 < 16; k16++)
            ldmx4(&afrag[k16 * 4], bBase + (uint32_t)(br * PADK + k16 * 16 + acolsel) * 2);
    }
    __syncthreads();

    // ---- B pipeline ----
    int q = lane >> 2, s4 = lane & 3;
    int rowA = wid * 16 + q, rowB = rowA + 8;
    float z1 = g_zsq[row0 + rowA], z2 = g_zsq[row0 + rowB];
    float rmin1 = FMAXV, rmin2 = FMAXV;
    int l = lane & 15;
    int brow_in = l & 7, bcolsel = ((l >> 3) & 1) * 8;

    // stage chunk 0
    {
        uint32_t dst = bBase;
        #pragma unroll
        for (int it = 0; it < 4; it++) {
            int u = it * 256 + tid; int rr = u >> 5, kk = (u & 31) * 8;
            cp16(dst + (uint32_t)(rr * PADK + kk) * 2, g_cbb + (size_t)(r * 1024 + rr) * 256 + kk);
        }
        asm volatile("cp.async.commit_group;");
    }

    for (int ch = 0; ch < 32; ch++) {
        asm volatile("cp.async.wait_group 0;");
        __syncthreads();
        if (ch + 1 < 32) {
            uint32_t dst = bBase + (uint32_t)((ch + 1) & 1) * BBUF;
            #pragma unroll
            for (int it = 0; it < 4; it++) {
                int u = it * 256 + tid; int rr = u >> 5, kk = (u & 31) * 8;
                cp16(dst + (uint32_t)(rr * PADK + kk) * 2,
                     g_cbb + (size_t)(r * 1024 + (ch + 1) * 32 + rr) * 256 + kk);
            }
            asm volatile("cp.async.commit_group;");
        }
        uint32_t bcur = bBase + (uint32_t)(ch & 1) * BBUF;
        float acc[4][4];
        #pragma unroll
        for (int nf = 0; nf < 4; nf++)
            #pragma unroll
            for (int v = 0; v < 4; v++) acc[nf][v] = 0.f;
        #pragma unroll
        for (int k16 = 0; k16 < 16; k16++) {
            uint32_t bfr[4][2];
            #pragma unroll
            for (int nf = 0; nf < 4; nf++)
                ldmx2(bfr[nf], bcur + (uint32_t)((nf * 8 + brow_in) * PADK + k16 * 16 + bcolsel) * 2);
            #pragma unroll
            for (int nf = 0; nf < 4; nf++)
                mma_bf16(acc[nf], &afrag[k16 * 4], bfr[nf]);
        }
        // epilogue (warp-local, no syncs)
        float m1 = FMAXV, m2 = FMAXV;
        #pragma unroll
        for (int nf = 0; nf < 4; nf++) {
            #pragma unroll
            for (int v = 0; v < 2; v++) {
                float cq = cbsq_s[ch * 32 + nf * 8 + s4 * 2 + v];
                m1 = fminf(m1, __fmaf_rn(-2.f, acc[nf][v], __fadd_rn(z1, cq)));
                m2 = fminf(m2, __fmaf_rn(-2.f, acc[nf][v + 2], __fadd_rn(z2, cq)));
            }
        }
        m1 = fminf(m1, __shfl_xor_sync(0xffffffffu, m1, 1));
        m1 = fminf(m1, __shfl_xor_sync(0xffffffffu, m1, 2));
        m2 = fminf(m2, __shfl_xor_sync(0xffffffffu, m2, 1));
        m2 = fminf(m2, __shfl_xor_sync(0xffffffffu, m2, 2));
        rmin1 = fminf(rmin1, m1);
        rmin2 = fminf(rmin2, m2);
        float t1 = rmin1 + EPSF, t2 = rmin2 + EPSF;
        #pragma unroll
        for (int nf = 0; nf < 4; nf++) {
            #pragma unroll
            for (int v = 0; v < 2; v++) {
                int col = ch * 32 + nf * 8 + s4 * 2 + v;
                float cq = cbsq_s[col - ch * 32 + ch * 32]; // = cbsq_s[ch*32 + ...]
                float d1 = __fmaf_rn(-2.f, acc[nf][v], __fadd_rn(z1, cq));
                if (d1 <= t1) {
                    int pos = atomicAdd(&cnt_s[rowA], 1);
                    if (pos < CCAP) {
                        g_cand[(size_t)(row0 + rowA) * CCAP + pos] = col;
                        g_candd[(size_t)(row0 + rowA) * CCAP + pos] = d1;
                    }
                }
                float d2 = __fmaf_rn(-2.f, acc[nf][v + 2], __fadd_rn(z2, cq));
                if (d2 <= t2) {
                    int pos = atomicAdd(&cnt_s[rowB], 1);
                    if (pos < CCAP) {
                        g_cand[(size_t)(row0 + rowB) * CCAP + pos] = col;
                        g_candd[(size_t)(row0 + rowB) * CCAP + pos] = d2;
                    }
                }
            }
        }
    }
    __syncthreads();
    if (tid < 128) g_cc[row0 + tid] = cnt_s[tid];
}

// ---- K3b: re-rank — d̃ prefilter + lane-parallel exact sequential chains ----
__device__ __forceinline__ float seq_d(const float* __restrict__ z, const float* __restrict__ cr,
                                       float zsqv, float cbsqj) {
    float acc = 0.f;
    #pragma unroll 8
    for (int k = 0; k < 256; k++) acc = __fmaf_rn(z[k], cr[k], acc);
    return __fmaf_rn(-2.0f, acc, __fadd_rn(zsqv, cbsqj));
}
__global__ void __launch_bounds__(256) p2_kernel(const float* __restrict__ H,
                                                 const float* __restrict__ cb) {
    int wid = threadIdx.x >> 5, lane = threadIdx.x & 31;
    int row = blockIdx.x * 8 + wid;
    int r = g_expert[row >> 10];
    const float* z = H + (size_t)row * 256;
    const float* cbase = cb + (size_t)r * 1024 * 256;
    const float* cbsq = g_cbsq + r * 1024;
    float zsqv = g_zsq[row];
    int c = g_cc[row];
    float best = FMAXV; int bestj = 0x7fffffff;
    if (c <= CCAP) {
        float dmin = FMAXV;
        for (int i0 = 0; i0 < c; i0 += 32) {
            float dv = (i0 + lane < c) ? g_candd[(size_t)row * CCAP + i0 + lane] : FMAXV;
            #pragma unroll
            for (int o = 16; o; o >>= 1) dv = fminf(dv, __shfl_xor_sync(0xffffffffu, dv, o));
            dmin = fminf(dmin, dv);
        }
        float thr = dmin + P2M;
        for (int i0 = 0; i0 < c; i0 += 32) {
            int idx = i0 + lane;
            float dv = (idx < c) ? g_candd[(size_t)row * CCAP + idx] : FMAXV;
            int j = (idx < c) ? g_cand[(size_t)row * CCAP + idx] : 0x7fffffff;
            float ds = FMAXV;
            if (dv <= thr) ds = seq_d(z, cbase + (size_t)j * 256, zsqv, cbsq[j]);
            else j = 0x7fffffff;
            #pragma unroll
            for (int o = 16; o; o >>= 1) {
                float od = __shfl_xor_sync(0xffffffffu, ds, o);
                int oj = __shfl_xor_sync(0xffffffffu, j, o);
                if (od < ds || (od == ds && oj < j)) { ds = od; j = oj; }
            }
            if (ds < best || (ds == best && j < bestj)) { best = ds; bestj = j; }
        }
    } else {
        for (int j0 = 0; j0 < 1024; j0 += 32) {
            int j = j0 + lane;
            float ds = seq_d(z, cbase + (size_t)j * 256, zsqv, cbsq[j]);
            #pragma unroll
            for (int o = 16; o; o >>= 1) {
                float od = __shfl_xor_sync(0xffffffffu, ds, o);
                int oj = __shfl_xor_sync(0xffffffffu, j, o);
                if (od < ds || (od == ds && oj < j)) { ds = od; j = oj; }
            }
            if (ds < best || (ds == best && j < bestj)) { best = ds; bestj = j; }
        }
    }
    if (lane == 0) g_indices[row] = bestj;
}

// ---- K4: z_q + SSE + indices ----
__global__ void __launch_bounds__(256) zq_kernel(const float* __restrict__ H,
                                                 const float* __restrict__ cb,
                                                 float* __restrict__ out) {
    __shared__ int sidx[16];
    __shared__ double red[256];
    int t = threadIdx.x;
    int row0 = blockIdx.x * 16;
    int r = g_expert[row0 >> 10];
    if (t < 16) {
        int row = row0 + t;
        int v = g_indices[row];
        sidx[t] = v;
        out[OFF_IND + row] = (float)v;
    }
    __syncthreads();
    double acc = 0.0;
    #pragma unroll
    for (int it = 0; it < 4; it++) {
        int qid = it * 256 + t;
        int rl = qid >> 6, qq = qid & 63;
        size_t row = (size_t)row0 + rl;
        float4 h = reinterpret_cast<const float4*>(H)[row * 64 + qq];
        float4 qv = reinterpret_cast<const float4*>(cb)[((size_t)r * 1024 + sidx[rl]) * 64 + qq];
        float dx = __fsub_rn(qv.x, h.x), dy = __fsub_rn(qv.y, h.y);
        float dz = __fsub_rn(qv.z, h.z), dw = __fsub_rn(qv.w, h.w);
        reinterpret_cast<float4*>(out + OFF_ZQ)[row * 64 + qq] =
            make_float4(__fadd_rn(h.x, dx), __fadd_rn(h.y, dy), __fadd_rn(h.z, dz), __fadd_rn(h.w, dw));
        acc += (double)__fmul_rn(dx, dx) + (double)__fmul_rn(dy, dy)
             + (double)__fmul_rn(dz, dz) + (double)__fmul_rn(dw, dw);
    }
    red[t] = acc;
    __syncthreads();
    for (int s = 128; s; s >>= 1) { if (t < s) red[t] += red[t + s]; __syncthreads(); }
    if (t == 0) atomicAdd(&g_sse, red[0]);
}

// ---- K5: QAM channel ----
__global__ void __launch_bounds__(256) channel_kernel() {
    int b = blockIdx.x;
    int m = g_phy[b];
    int bps = (m == 0) ? 2 : (m == 1) ? 4 : 6;
    int n_sym = PADB / bps;
    int mside = (m == 0) ? 2 : (m == 1) ? 4 : 8;
    int M = mside * mside;
    float std_ = g_std;
    __shared__ float cx[64], cy[64];
    __shared__ uint32_t skey[2];
    if (threadIdx.x < M) {
        double mean = (m == 0) ? 2.0 : (m == 1) ? 10.0 : 42.0;
        double norm = sqrt(mean + 1e-9);
        int i = threadIdx.x / mside, j = threadIdx.x % mside;
        cx[threadIdx.x] = (float)((double)(-(mside - 1) + 2 * i) / norm);
        cy[threadIdx.x] = (float)((double)(-(mside - 1) + 2 * j) / norm);
    }
    if (threadIdx.x == 0) {
        uint32_t o0, o1;
        threefry2x32(0u, 42u, 0u, (uint32_t)m, o0, o1);
        skey[0] = o0; skey[1] = o1;
    }
    __syncthreads();
    uint32_t k0 = skey[0], k1 = skey[1];
    const int* idxrow = g_indices + b * NN;
    uint8_t* bitrow = g_bits + b * PADB;
    for (int s = threadIdx.x; s < n_sym; s += 256) {
        int p0 = s * bps, sym = 0;
        for (int j = 0; j < bps; j++) {
            int p = p0 + j, bit = 0;
            if (p < TOTB) bit = (idxrow[p / 10] >> (9 - p % 10)) & 1;
            sym = (sym << 1) | bit;
        }
        float tx0 = cx[sym], tx1 = cy[sym];
        uint32_t i0 = (uint32_t)(b * n_sym + s) * 2u;
        float rx0 = __fadd_rn(tx0, __fmul_rn(std_, gen_normal_part(k0, k1, i0)));
        float rx1 = __fadd_rn(tx1, __fmul_rn(std_, gen_normal_part(k0, k1, i0 + 1u)));
        float best = FMAXV; int bi = 0;
        for (int k = 0; k < M; k++) {
            float dx = __fsub_rn(rx0, cx[k]), dy = __fsub_rn(rx1, cy[k]);
            float d = __fadd_rn(__fmul_rn(dx, dx), __fmul_rn(dy, dy));
            if (d < best) { best = d; bi = k; }
        }
        for (int j = 0; j < bps; j++)
            bitrow[p0 + j] = (uint8_t)((bi >> (bps - 1 - j)) & 1);
    }
}

// ---- K6: idx_hat + H_hat + vq_loss ----
__global__ void __launch_bounds__(256) final_kernel(const float* __restrict__ H,
                                                    const float* __restrict__ cb,
                                                    float* __restrict__ out) {
    __shared__ int sidx[16];
    int t = threadIdx.x;
    int row0 = blockIdx.x * 16;
    int b = row0 >> 10;
    int r = g_expert[b];
    if (t < 16) {
        int row = row0 + t;
        int n = row & (NN - 1);
        const uint8_t* bt = g_bits + b * PADB + n * 10;
        int v = 0;
        #pragma unroll
        for (int j = 0; j < 10; j++) v = (v << 1) | bt[j];
        if (v > NK - 1) v = NK - 1;
        sidx[t] = v;
        out[OFF_IDXHAT + row] = (float)v;
    }
    __syncthreads();
    #pragma unroll
    for (int it = 0; it < 4; it++) {
        int qid = it * 256 + t;
        int rl = qid >> 6, qq = qid & 63;
        size_t row = (size_t)row0 + rl;
        float4 h = reinterpret_cast<const float4*>(H)[row * 64 + qq];
        float4 c = reinterpret_cast<const float4*>(cb)[((size_t)r * 1024 + sidx[rl]) * 64 + qq];
        reinterpret_cast<float4*>(out + OFF_HHAT)[row * 64 + qq] =
            make_float4(__fadd_rn(h.x, __fsub_rn(c.x, h.x)), __fadd_rn(h.y, __fsub_rn(c.y, h.y)),
                        __fadd_rn(h.z, __fsub_rn(c.z, h.z)), __fadd_rn(h.w, __fsub_rn(c.w, h.w)));
    }
    if (blockIdx.x == 0 && t == 0) {
        double denom = (double)NB * (double)NN * (double)NCH * (double)NCH;
        out[OFF_VQ] = (float)(1.25 * g_sse / denom);
    }
}

// ---- launch ----
extern "C" void kernel_launch(void* const* d_in, const int* in_sizes, int n_in,
                              void* d_out, int out_size) {
    const float* H         = (const float*)d_in[0];
    const float* phi       = (const float*)d_in[1];
    const float* w0        = (const float*)d_in[2];
    const float* b0        = (const float*)d_in[3];
    const float* w1        = (const float*)d_in[4];
    const float* b1        = (const float*)d_in[5];
    const float* w2        = (const float*)d_in[6];
    const float* b2        = (const float*)d_in[7];
    const float* codebooks = (const float*)d_in[8];
    const float* noise_var = (const float*)d_in[9];
    float* out = (float*)d_out;

    cudaFuncSetAttribute(vqm_kernel, cudaFuncAttributeMaxDynamicSharedMemorySize, S3_TOT);

    prep_kernel<<<(NB * NN * NCH / 4 + NR * NK * NCH / 4 + 255) / 256, 256>>>(H, codebooks);
    mlp_kernel<<<NB, 128>>>(phi, w0, b0, w1, b1, w2, b2, noise_var, out);
    sq_kernel<<<(NB * NN + NR * NK + 7) / 8, 256>>>(H, codebooks);
    vqm_kernel<<<NB * NN / 128, 256, S3_TOT>>>();
    p2_kernel<<<NB * NN / 8, 256>>>(H, codebooks);
    zq_kernel<<<NB * NN / 16, 256>>>(H, codebooks, out);
    channel_kernel<<<NB, 256>>>();
    final_kernel<<<NB * NN / 16, 256>>>(H, codebooks, out);
}

// round 11
// speedup vs baseline: 2.2750x; 1.1434x over previous
#include <cuda_runtime.h>
#include <cuda_bf16.h>
#include <stdint.h>
#include <math.h>

#define NB 64
#define NN 1024
#define NCH 256
#define NR 4
#define NK 1024
#define TOTB 10240
#define PADB 10248
#define EPSF 0.25f
#define P2M  0.1f
#define CCAP 128
#define FMAXV 3.402823466e+38f

#define OFF_HHAT   0LL
#define OFF_ZQ     16777216LL
#define OFF_IND    33554432LL
#define OFF_IDXHAT 33619968LL
#define OFF_VQ     33685504LL
#define OFF_LOGITS 33685505LL
#define OFF_PROBS  33686273LL
#define OFF_MODE   33687041LL

__device__ int     g_expert[NB];
__device__ int     g_phy[NB];
__device__ float   g_std;
__device__ float   g_zsq[NB * NN];
__device__ float   g_cbsq[NR * NK];
__device__ int     g_indices[NB * NN];
__device__ uint8_t g_bits[NB * PADB];
__device__ double  g_ssep[8192];
__device__ __align__(16) __nv_bfloat16 g_Hb[NB * NN * NCH];
__device__ __align__(16) __nv_bfloat16 g_cbb[NR * NK * NCH];
__device__ int   g_cand[(size_t)NB * NN * CCAP];
__device__ float g_candd[(size_t)NB * NN * CCAP];
__device__ int   g_cc[NB * NN];

// ---- helpers ----
__device__ __forceinline__ uint32_t smem_to_u32(const void* p) {
    uint32_t a;
    asm("{ .reg .u64 t; cvta.to.shared.u64 t, %1; cvt.u32.u64 %0, t; }" : "=r"(a) : "l"(p));
    return a;
}
__device__ __forceinline__ void ldmx4(uint32_t* r, uint32_t addr) {
    asm volatile("ldmatrix.sync.aligned.m8n8.x4.shared.b16 {%0,%1,%2,%3}, [%4];"
        : "=r"(r[0]), "=r"(r[1]), "=r"(r[2]), "=r"(r[3]) : "r"(addr));
}
__device__ __forceinline__ void ldmx2(uint32_t* r, uint32_t addr) {
    asm volatile("ldmatrix.sync.aligned.m8n8.x2.shared.b16 {%0,%1}, [%2];"
        : "=r"(r[0]), "=r"(r[1]) : "r"(addr));
}
__device__ __forceinline__ void mma_bf16(float* c, const uint32_t* a, const uint32_t* b) {
    asm volatile("mma.sync.aligned.m16n8k16.row.col.f32.bf16.bf16.f32 "
        "{%0,%1,%2,%3}, {%4,%5,%6,%7}, {%8,%9}, {%0,%1,%2,%3};"
        : "+f"(c[0]), "+f"(c[1]), "+f"(c[2]), "+f"(c[3])
        : "r"(a[0]), "r"(a[1]), "r"(a[2]), "r"(a[3]), "r"(b[0]), "r"(b[1]));
}
__device__ __forceinline__ void cp16(uint32_t dst, const void* src) {
    asm volatile("cp.async.cg.shared.global [%0], [%1], 16;" :: "r"(dst), "l"(src));
}

// ---- threefry (JAX) ----
__device__ __forceinline__ uint32_t rotl32(uint32_t x, int r) { return (x << r) | (x >> (32 - r)); }
__device__ __forceinline__ void threefry2x32(uint32_t k0, uint32_t k1, uint32_t x0, uint32_t x1,
                                             uint32_t& o0, uint32_t& o1) {
    uint32_t k2 = k0 ^ k1 ^ 0x1BD11BDAu;
    x0 += k0; x1 += k1;
#define TF_R(a) x0 += x1; x1 = rotl32(x1, a); x1 ^= x0;
#define TF_G(a,b,c,d) TF_R(a) TF_R(b) TF_R(c) TF_R(d)
    TF_G(13, 15, 26, 6)  x0 += k1; x1 += k2 + 1u;
    TF_G(17, 29, 16, 24) x0 += k2; x1 += k0 + 2u;
    TF_G(13, 15, 26, 6)  x0 += k0; x1 += k1 + 3u;
    TF_G(17, 29, 16, 24) x0 += k1; x1 += k2 + 4u;
    TF_G(13, 15, 26, 6)  x0 += k2; x1 += k0 + 5u;
#undef TF_G
#undef TF_R
    o0 = x0; o1 = x1;
}
__device__ __forceinline__ float jax_normal_from_bits(uint32_t bits) {
    float u1 = __uint_as_float(0x3f800000u | (bits >> 9)) - 1.0f;
    const float lo = __uint_as_float(0xBF7FFFFFu);
    float u = __fadd_rn(__fmul_rn(u1, 2.0f), lo);
    u = fmaxf(u, lo);
    float w = -log1pf(-__fmul_rn(u, u));
    float p;
    if (w < 5.0f) {
        w = __fsub_rn(w, 2.5f);
        p = 2.81022636e-08f;
        p = __fmaf_rn(p, w, 3.43273939e-07f);
        p = __fmaf_rn(p, w, -3.5233877e-06f);
        p = __fmaf_rn(p, w, -4.39150654e-06f);
        p = __fmaf_rn(p, w, 0.00021858087f);
        p = __fmaf_rn(p, w, -0.00125372503f);
        p = __fmaf_rn(p, w, -0.00417768164f);
        p = __fmaf_rn(p, w, 0.246640727f);
        p = __fmaf_rn(p, w, 1.50140941f);
    } else {
        w = __fsub_rn(sqrtf(w), 3.0f);
        p = -0.000200214257f;
        p = __fmaf_rn(p, w, 0.000100950558f);
        p = __fmaf_rn(p, w, 0.00134934322f);
        p = __fmaf_rn(p, w, -0.00367342844f);
        p = __fmaf_rn(p, w, 0.00573950773f);
        p = __fmaf_rn(p, w, -0.0076224613f);
        p = __fmaf_rn(p, w, 0.00943887047f);
        p = __fmaf_rn(p, w, 1.00167406f);
        p = __fmaf_rn(p, w, 2.83297682f);
    }
    return __fmul_rn(__uint_as_float(0x3FB504F3u), __fmul_rn(p, u));
}
__device__ __forceinline__ float gen_normal_part(uint32_t k0, uint32_t k1, uint32_t i) {
    uint32_t o0, o1;
    threefry2x32(k0, k1, 0u, i, o0, o1);
    return jax_normal_from_bits(o0 ^ o1);
}

// ---- K0: bf16 convert ----
__global__ void __launch_bounds__(256) prep_kernel(const float* __restrict__ H,
                                                   const float* __restrict__ cb) {
    int i = blockIdx.x * 256 + threadIdx.x;
    const int NH4 = NB * NN * NCH / 4, NC4 = NR * NK * NCH / 4;
    if (i < NH4) {
        float4 v = reinterpret_cast<const float4*>(H)[i];
        __nv_bfloat162 p0 = __floats2bfloat162_rn(v.x, v.y), p1 = __floats2bfloat162_rn(v.z, v.w);
        reinterpret_cast<uint2*>(g_Hb)[i] = make_uint2(*(uint32_t*)&p0, *(uint32_t*)&p1);
    } else if (i - NH4 < NC4) {
        int j = i - NH4;
        float4 v = reinterpret_cast<const float4*>(cb)[j];
        __nv_bfloat162 p0 = __floats2bfloat162_rn(v.x, v.y), p1 = __floats2bfloat162_rn(v.z, v.w);
        reinterpret_cast<uint2*>(g_cbb)[j] = make_uint2(*(uint32_t*)&p0, *(uint32_t*)&p1);
    }
}

// ---- K1: router MLP ----
__global__ void __launch_bounds__(128) mlp_kernel(
    const float* __restrict__ phi, const float* __restrict__ w0, const float* __restrict__ b0,
    const float* __restrict__ w1, const float* __restrict__ b1, const float* __restrict__ w2,
    const float* __restrict__ b2, const float* __restrict__ noise_var, float* __restrict__ out) {
    __shared__ float sphi[512], sh[128], sh2[128], sl[12];
    int b = blockIdx.x, t = threadIdx.x;
    for (int d = t; d < 512; d += 128) sphi[d] = phi[b * 512 + d];
    __syncthreads();
    float a = 0.f;
    #pragma unroll 8
    for (int d = 0; d < 512; d++) a = __fmaf_rn(sphi[d], w0[d * 128 + t], a);
    sh[t] = fmaxf(__fadd_rn(a, b0[t]), 0.f);
    __syncthreads();
    float a2 = 0.f;
    #pragma unroll 8
    for (int i = 0; i < 128; i++) a2 = __fmaf_rn(sh[i], w1[i * 128 + t], a2);
    sh2[t] = fmaxf(__fadd_rn(a2, b1[t]), 0.f);
    __syncthreads();
    if (t < 12) {
        float l = 0.f;
        for (int i = 0; i < 128; i++) l = __fmaf_rn(sh2[i], w2[i * 12 + t], l);
        l = __fadd_rn(l, b2[t]);
        sl[t] = l;
        out[OFF_LOGITS + b * 12 + t] = l;
    }
    __syncthreads();
    if (t == 0) {
        float mx = sl[0]; int mi = 0;
        for (int j = 1; j < 12; j++) if (sl[j] > mx) { mx = sl[j]; mi = j; }
        float e[12], s = 0.f;
        for (int j = 0; j < 12; j++) { e[j] = expf(__fsub_rn(sl[j], mx)); s = __fadd_rn(s, e[j]); }
        for (int j = 0; j < 12; j++) out[OFF_PROBS + b * 12 + j] = __fdiv_rn(e[j], s);
        out[OFF_MODE + b] = (float)mi;
        g_expert[b] = mi / 3;
        g_phy[b] = mi % 3;
        if (b == 0) g_std = sqrtf(fmaxf(noise_var[0], 0.f));
    }
}

// ---- K2: row squared norms (ordering validated — do not touch) ----
__global__ void __launch_bounds__(256) sq_kernel(const float* __restrict__ H,
                                                 const float* __restrict__ cb) {
    int warp = (blockIdx.x * blockDim.x + threadIdx.x) >> 5;
    int lane = threadIdx.x & 31;
    const int TOT = NB * NN + NR * NK;
    if (warp >= TOT) return;
    const float* src = (warp < NB * NN) ? (H + (size_t)warp * NCH) : (cb + (size_t)(warp - NB * NN) * NCH);
    double s = 0.0;
    #pragma unroll
    for (int c = lane; c < NCH; c += 32) { float v = src[c]; s += (double)__fmul_rn(v, v); }
    #pragma unroll
    for (int o = 16; o; o >>= 1) s += __shfl_down_sync(0xffffffffu, s, o);
    if (lane == 0) { if (warp < NB * NN) g_zsq[warp] = (float)s; else g_cbsq[warp - NB * NN] = (float)s; }
}

// ---- K3: A-in-register bf16 mma, 32-col B chunks double-buffered (validated) ----
#define PADK 264
#define BBUF 16896
#define S3_CBSQ 0
#define S3_CNT 4096
#define S3_B 4608
#define S3_TOT 38400

__global__ void __launch_bounds__(256, 2) vqm_kernel() {
    extern __shared__ char smem[];
    float* cbsq_s = (float*)(smem + S3_CBSQ);
    int* cnt_s = (int*)(smem + S3_CNT);
    uint32_t bBase = smem_to_u32(smem + S3_B);

    int tid = threadIdx.x, wid = tid >> 5, lane = tid & 31;
    int row0 = blockIdx.x * 128;
    int r = g_expert[row0 >> 10];
    for (int j = tid; j < 1024; j += 256) cbsq_s[j] = g_cbsq[r * 1024 + j];
    if (tid < 128) cnt_s[tid] = 0;

    uint32_t afrag[64];
    int arow_in = (lane & 7) + ((lane >> 3) & 1) * 8;
    int acolsel = (lane >> 4) * 8;
    #pragma unroll
    for (int it = 0; it < 8; it++) {
        int u = it * 256 + tid; int rr = u >> 5, kk = (u & 31) * 8;
        cp16(bBase + (uint32_t)(rr * PADK + kk) * 2, g_Hb + (size_t)(row0 + rr) * 256 + kk);
    }
    asm volatile("cp.async.commit_group;");
    asm volatile("cp.async.wait_group 0;");
    __syncthreads();
    if (wid < 4) {
        int br = wid * 16 + arow_in;
        #pragma unroll
        for (int k16 = 0; k16 < 16; k16++)
            ldmx4(&afrag[k16 * 4], bBase + (uint32_t)(br * PADK + k16 * 16 + acolsel) * 2);
    }
    __syncthreads();
    #pragma unroll
    for (int it = 0; it < 8; it++) {
        int u = it * 256 + tid; int rr = u >> 5, kk = (u & 31) * 8;
        cp16(bBase + (uint32_t)(rr * PADK + kk) * 2, g_Hb + (size_t)(row0 + 64 + rr) * 256 + kk);
    }
    asm volatile("cp.async.commit_group;");
    asm volatile("cp.async.wait_group 0;");
    __syncthreads();
    if (wid >= 4) {
        int br = (wid - 4) * 16 + arow_in;
        #pragma unroll
        for (int k16 = 0; k16 < 16; k16++)
            ldmx4(&afrag[k16 * 4], bBase + (uint32_t)(br * PADK + k16 * 16 + acolsel) * 2);
    }
    __syncthreads();

    int q = lane >> 2, s4 = lane & 3;
    int rowA = wid * 16 + q, rowB = rowA + 8;
    float z1 = g_zsq[row0 + rowA], z2 = g_zsq[row0 + rowB];
    float rmin1 = FMAXV, rmin2 = FMAXV;
    int l = lane & 15;
    int brow_in = l & 7, bcolsel = ((l >> 3) & 1) * 8;

    {
        uint32_t dst = bBase;
        #pragma unroll
        for (int it = 0; it < 4; it++) {
            int u = it * 256 + tid; int rr = u >> 5, kk = (u & 31) * 8;
            cp16(dst + (uint32_t)(rr * PADK + kk) * 2, g_cbb + (size_t)(r * 1024 + rr) * 256 + kk);
        }
        asm volatile("cp.async.commit_group;");
    }

    for (int ch = 0; ch < 32; ch++) {
        asm volatile("cp.async.wait_group 0;");
        __syncthreads();
        if (ch + 1 < 32) {
            uint32_t dst = bBase + (uint32_t)((ch + 1) & 1) * BBUF;
            #pragma unroll
            for (int it = 0; it < 4; it++) {
                int u = it * 256 + tid; int rr = u >> 5, kk = (u & 31) * 8;
                cp16(dst + (uint32_t)(rr * PADK + kk) * 2,
                     g_cbb + (size_t)(r * 1024 + (ch + 1) * 32 + rr) * 256 + kk);
            }
            asm volatile("cp.async.commit_group;");
        }
        uint32_t bcur = bBase + (uint32_t)(ch & 1) * BBUF;
        float acc[4][4];
        #pragma unroll
        for (int nf = 0; nf < 4; nf++)
            #pragma unroll
            for (int v = 0; v < 4; v++) acc[nf][v] = 0.f;
        #pragma unroll
        for (int k16 = 0; k16 < 16; k16++) {
            uint32_t bfr[4][2];
            #pragma unroll
            for (int nf = 0; nf < 4; nf++)
                ldmx2(bfr[nf], bcur + (uint32_t)((nf * 8 + brow_in) * PADK + k16 * 16 + bcolsel) * 2);
            #pragma unroll
            for (int nf = 0; nf < 4; nf++)
                mma_bf16(acc[nf], &afrag[k16 * 4], bfr[nf]);
        }
        float m1 = FMAXV, m2 = FMAXV;
        #pragma unroll
        for (int nf = 0; nf < 4; nf++) {
            #pragma unroll
            for (int v = 0; v < 2; v++) {
                float cq = cbsq_s[ch * 32 + nf * 8 + s4 * 2 + v];
                m1 = fminf(m1, __fmaf_rn(-2.f, acc[nf][v], __fadd_rn(z1, cq)));
                m2 = fminf(m2, __fmaf_rn(-2.f, acc[nf][v + 2], __fadd_rn(z2, cq)));
            }
        }
        m1 = fminf(m1, __shfl_xor_sync(0xffffffffu, m1, 1));
        m1 = fminf(m1, __shfl_xor_sync(0xffffffffu, m1, 2));
        m2 = fminf(m2, __shfl_xor_sync(0xffffffffu, m2, 1));
        m2 = fminf(m2, __shfl_xor_sync(0xffffffffu, m2, 2));
        rmin1 = fminf(rmin1, m1);
        rmin2 = fminf(rmin2, m2);
        float t1 = rmin1 + EPSF, t2 = rmin2 + EPSF;
        #pragma unroll
        for (int nf = 0; nf < 4; nf++) {
            #pragma unroll
            for (int v = 0; v < 2; v++) {
                int col = ch * 32 + nf * 8 + s4 * 2 + v;
                float cq = cbsq_s[col];
                float d1 = __fmaf_rn(-2.f, acc[nf][v], __fadd_rn(z1, cq));
                if (d1 <= t1) {
                    int pos = atomicAdd(&cnt_s[rowA], 1);
                    if (pos < CCAP) {
                        g_cand[(size_t)(row0 + rowA) * CCAP + pos] = col;
                        g_candd[(size_t)(row0 + rowA) * CCAP + pos] = d1;
                    }
                }
                float d2 = __fmaf_rn(-2.f, acc[nf][v + 2], __fadd_rn(z2, cq));
                if (d2 <= t2) {
                    int pos = atomicAdd(&cnt_s[rowB], 1);
                    if (pos < CCAP) {
                        g_cand[(size_t)(row0 + rowB) * CCAP + pos] = col;
                        g_candd[(size_t)(row0 + rowB) * CCAP + pos] = d2;
                    }
                }
            }
        }
    }
    __syncthreads();
    if (tid < 128) g_cc[row0 + tid] = cnt_s[tid];
}

// ---- K3b: re-rank + fused z_q/SSE/indices ----
__device__ __forceinline__ float seq_d(const float* __restrict__ z, const float* __restrict__ cr,
                                       float zsqv, float cbsqj) {
    float acc = 0.f;
    #pragma unroll 8
    for (int k = 0; k < 256; k++) acc = __fmaf_rn(z[k], cr[k], acc);
    return __fmaf_rn(-2.0f, acc, __fadd_rn(zsqv, cbsqj));
}
__global__ void __launch_bounds__(256) p2_kernel(const float* __restrict__ H,
                                                 const float* __restrict__ cb,
                                                 float* __restrict__ out) {
    __shared__ double ssep[8];
    int wid = threadIdx.x >> 5, lane = threadIdx.x & 31;
    int row = blockIdx.x * 8 + wid;
    int r = g_expert[row >> 10];
    const float* z = H + (size_t)row * 256;
    const float* cbase = cb + (size_t)r * 1024 * 256;
    const float* cbsq = g_cbsq + r * 1024;
    float zsqv = g_zsq[row];
    int c = g_cc[row];
    float best = FMAXV; int bestj = 0x7fffffff;
    if (c <= CCAP) {
        float dmin = FMAXV;
        for (int i0 = 0; i0 < c; i0 += 32) {
            float dv = (i0 + lane < c) ? g_candd[(size_t)row * CCAP + i0 + lane] : FMAXV;
            #pragma unroll
            for (int o = 16; o; o >>= 1) dv = fminf(dv, __shfl_xor_sync(0xffffffffu, dv, o));
            dmin = fminf(dmin, dv);
        }
        float thr = dmin + P2M;
        for (int i0 = 0; i0 < c; i0 += 32) {
            int idx = i0 + lane;
            float dv = (idx < c) ? g_candd[(size_t)row * CCAP + idx] : FMAXV;
            int j = (idx < c) ? g_cand[(size_t)row * CCAP + idx] : 0x7fffffff;
            float ds = FMAXV;
            if (dv <= thr) ds = seq_d(z, cbase + (size_t)j * 256, zsqv, cbsq[j]);
            else j = 0x7fffffff;
            #pragma unroll
            for (int o = 16; o; o >>= 1) {
                float od = __shfl_xor_sync(0xffffffffu, ds, o);
                int oj = __shfl_xor_sync(0xffffffffu, j, o);
                if (od < ds || (od == ds && oj < j)) { ds = od; j = oj; }
            }
            if (ds < best || (ds == best && j < bestj)) { best = ds; bestj = j; }
        }
    } else {
        for (int j0 = 0; j0 < 1024; j0 += 32) {
            int j = j0 + lane;
            float ds = seq_d(z, cbase + (size_t)j * 256, zsqv, cbsq[j]);
            #pragma unroll
            for (int o = 16; o; o >>= 1) {
                float od = __shfl_xor_sync(0xffffffffu, ds, o);
                int oj = __shfl_xor_sync(0xffffffffu, j, o);
                if (od < ds || (od == ds && oj < j)) { ds = od; j = oj; }
            }
            if (ds < best || (ds == best && j < bestj)) { best = ds; bestj = j; }
        }
    }
    // fused z_q / SSE / indices (bestj identical in all lanes after butterfly)
    if (lane == 0) {
        g_indices[row] = bestj;
        out[OFF_IND + row] = (float)bestj;
    }
    const float* cr = cbase + (size_t)bestj * 256;
    double acc = 0.0;
    #pragma unroll
    for (int t = 0; t < 8; t++) {
        int k = lane + 32 * t;
        float h = z[k];
        float dlt = __fsub_rn(cr[k], h);
        out[OFF_ZQ + (size_t)row * 256 + k] = __fadd_rn(h, dlt);
        acc += (double)__fmul_rn(dlt, dlt);
    }
    #pragma unroll
    for (int o = 16; o; o >>= 1) acc += __shfl_down_sync(0xffffffffu, acc, o);
    if (lane == 0) ssep[wid] = acc;
    __syncthreads();
    if (threadIdx.x == 0) {
        double s = 0.0;
        #pragma unroll
        for (int w = 0; w < 8; w++) s += ssep[w];
        g_ssep[blockIdx.x] = s;
    }
}

// ---- K5: QAM channel (symbol-parallel) ----
__global__ void __launch_bounds__(256) channel_kernel() {
    int b = blockIdx.x;
    int m = g_phy[b];
    int bps = (m == 0) ? 2 : (m == 1) ? 4 : 6;
    int n_sym = PADB / bps;
    int mside = (m == 0) ? 2 : (m == 1) ? 4 : 8;
    int M = mside * mside;
    float std_ = g_std;
    __shared__ float cx[64], cy[64];
    __shared__ uint32_t skey[2];
    if (threadIdx.x < M) {
        double mean = (m == 0) ? 2.0 : (m == 1) ? 10.0 : 42.0;
        double norm = sqrt(mean + 1e-9);
        int i = threadIdx.x / mside, j = threadIdx.x % mside;
        cx[threadIdx.x] = (float)((double)(-(mside - 1) + 2 * i) / norm);
        cy[threadIdx.x] = (float)((double)(-(mside - 1) + 2 * j) / norm);
    }
    if (threadIdx.x == 0) {
        uint32_t o0, o1;
        threefry2x32(0u, 42u, 0u, (uint32_t)m, o0, o1);
        skey[0] = o0; skey[1] = o1;
    }
    __syncthreads();
    int s = blockIdx.y * 256 + threadIdx.x;
    if (s >= n_sym) return;
    uint32_t k0 = skey[0], k1 = skey[1];
    const int* idxrow = g_indices + b * NN;
    uint8_t* bitrow = g_bits + b * PADB;
    int p0 = s * bps, sym = 0;
    for (int j = 0; j < bps; j++) {
        int p = p0 + j, bit = 0;
        if (p < TOTB) bit = (idxrow[p / 10] >> (9 - p % 10)) & 1;
        sym = (sym << 1) | bit;
    }
    float tx0 = cx[sym], tx1 = cy[sym];
    uint32_t i0 = (uint32_t)(b * n_sym + s) * 2u;
    float rx0 = __fadd_rn(tx0, __fmul_rn(std_, gen_normal_part(k0, k1, i0)));
    float rx1 = __fadd_rn(tx1, __fmul_rn(std_, gen_normal_part(k0, k1, i0 + 1u)));
    float best = FMAXV; int bi = 0;
    for (int k = 0; k < M; k++) {
        float dx = __fsub_rn(rx0, cx[k]), dy = __fsub_rn(rx1, cy[k]);
        float d = __fadd_rn(__fmul_rn(dx, dx), __fmul_rn(dy, dy));
        if (d < best) { best = d; bi = k; }
    }
    for (int j = 0; j < bps; j++)
        bitrow[p0 + j] = (uint8_t)((bi >> (bps - 1 - j)) & 1);
}

// ---- K6: idx_hat + H_hat + vq_loss (block 0 reduces SSE partials) ----
__global__ void __launch_bounds__(256) final_kernel(const float* __restrict__ H,
                                                    const float* __restrict__ cb,
                                                    float* __restrict__ out) {
    __shared__ int sidx[16];
    __shared__ double sred[256];
    int t = threadIdx.x;
    int row0 = blockIdx.x * 16;
    int b = row0 >> 10;
    int r = g_expert[b];
    if (t < 16) {
        int row = row0 + t;
        int n = row & (NN - 1);
        const uint8_t* bt = g_bits + b * PADB + n * 10;
        int v = 0;
        #pragma unroll
        for (int j = 0; j < 10; j++) v = (v << 1) | bt[j];
        if (v > NK - 1) v = NK - 1;
        sidx[t] = v;
        out[OFF_IDXHAT + row] = (float)v;
    }
    __syncthreads();
    #pragma unroll
    for (int it = 0; it < 4; it++) {
        int qid = it * 256 + t;
        int rl = qid >> 6, qq = qid & 63;
        size_t row = (size_t)row0 + rl;
        float4 h = reinterpret_cast<const float4*>(H)[row * 64 + qq];
        float4 c = reinterpret_cast<const float4*>(cb)[((size_t)r * 1024 + sidx[rl]) * 64 + qq];
        reinterpret_cast<float4*>(out + OFF_HHAT)[row * 64 + qq] =
            make_float4(__fadd_rn(h.x, __fsub_rn(c.x, h.x)), __fadd_rn(h.y, __fsub_rn(c.y, h.y)),
                        __fadd_rn(h.z, __fsub_rn(c.z, h.z)), __fadd_rn(h.w, __fsub_rn(c.w, h.w)));
    }
    if (blockIdx.x == 0) {
        double s = 0.0;
        for (int i = t; i < 8192; i += 256) s += g_ssep[i];
        sred[t] = s;
        __syncthreads();
        for (int st = 128; st; st >>= 1) {
            if (t < st) sred[t] += sred[t + st];
            __syncthreads();
        }
        if (t == 0) {
            double denom = (double)NB * (double)NN * (double)NCH * (double)NCH;
            out[OFF_VQ] = (float)(1.25 * sred[0] / denom);
        }
    }
}

// ---- launch ----
extern "C" void kernel_launch(void* const* d_in, const int* in_sizes, int n_in,
                              void* d_out, int out_size) {
    const float* H         = (const float*)d_in[0];
    const float* phi       = (const float*)d_in[1];
    const float* w0        = (const float*)d_in[2];
    const float* b0        = (const float*)d_in[3];
    const float* w1        = (const float*)d_in[4];
    const float* b1        = (const float*)d_in[5];
    const float* w2        = (const float*)d_in[6];
    const float* b2        = (const float*)d_in[7];
    const float* codebooks = (const float*)d_in[8];
    const float* noise_var = (const float*)d_in[9];
    float* out = (float*)d_out;

    cudaFuncSetAttribute(vqm_kernel, cudaFuncAttributeMaxDynamicSharedMemorySize, S3_TOT);

    prep_kernel<<<(NB * NN * NCH / 4 + NR * NK * NCH / 4 + 255) / 256, 256>>>(H, codebooks);
    mlp_kernel<<<NB, 128>>>(phi, w0, b0, w1, b1, w2, b2, noise_var, out);
    sq_kernel<<<(NB * NN + NR * NK + 7) / 8, 256>>>(H, codebooks);
    vqm_kernel<<<NB * NN / 128, 256, S3_TOT>>>();
    p2_kernel<<<NB * NN / 8, 256>>>(H, codebooks, out);
    channel_kernel<<<dim3(NB, 21), 256>>>();
    final_kernel<<<NB * NN / 16, 256>>>(H, codebooks, out);
}

// round 12
// speedup vs baseline: 2.3657x; 1.0398x over previous
#include <cuda_runtime.h>
#include <cuda_bf16.h>
#include <stdint.h>
#include <math.h>

#define NB 64
#define NN 1024
#define NCH 256
#define NR 4
#define NK 1024
#define TOTB 10240
#define PADB 10248
#define EPSF 0.25f
#define P2M  0.1f
#define CCAP 128
#define FMAXV 3.402823466e+38f

#define OFF_HHAT   0LL
#define OFF_ZQ     16777216LL
#define OFF_IND    33554432LL
#define OFF_IDXHAT 33619968LL
#define OFF_VQ     33685504LL
#define OFF_LOGITS 33685505LL
#define OFF_PROBS  33686273LL
#define OFF_MODE   33687041LL

__device__ int     g_expert[NB];
__device__ int     g_phy[NB];
__device__ float   g_std;
__device__ float   g_zsq[NB * NN];
__device__ float   g_cbsq[NR * NK];
__device__ int     g_indices[NB * NN];
__device__ uint8_t g_bits[NB * PADB];
__device__ double  g_ssep[8192];
__device__ __align__(16) __nv_bfloat16 g_Hb[NB * NN * NCH];
__device__ __align__(16) __nv_bfloat16 g_cbb[NR * NK * NCH];
__device__ int   g_cand[(size_t)NB * NN * CCAP];
__device__ float g_candd[(size_t)NB * NN * CCAP];
__device__ int   g_cc[NB * NN];

// ---- helpers ----
__device__ __forceinline__ uint32_t smem_to_u32(const void* p) {
    uint32_t a;
    asm("{ .reg .u64 t; cvta.to.shared.u64 t, %1; cvt.u32.u64 %0, t; }" : "=r"(a) : "l"(p));
    return a;
}
__device__ __forceinline__ void ldmx4(uint32_t* r, uint32_t addr) {
    asm volatile("ldmatrix.sync.aligned.m8n8.x4.shared.b16 {%0,%1,%2,%3}, [%4];"
        : "=r"(r[0]), "=r"(r[1]), "=r"(r[2]), "=r"(r[3]) : "r"(addr));
}
__device__ __forceinline__ void mma_bf16(float* c, const uint32_t* a, const uint32_t* b) {
    asm volatile("mma.sync.aligned.m16n8k16.row.col.f32.bf16.bf16.f32 "
        "{%0,%1,%2,%3}, {%4,%5,%6,%7}, {%8,%9}, {%0,%1,%2,%3};"
        : "+f"(c[0]), "+f"(c[1]), "+f"(c[2]), "+f"(c[3])
        : "r"(a[0]), "r"(a[1]), "r"(a[2]), "r"(a[3]), "r"(b[0]), "r"(b[1]));
}
__device__ __forceinline__ void cp16(uint32_t dst, const void* src) {
    asm volatile("cp.async.cg.shared.global [%0], [%1], 16;" :: "r"(dst), "l"(src));
}

// ---- threefry (JAX) ----
__device__ __forceinline__ uint32_t rotl32(uint32_t x, int r) { return (x << r) | (x >> (32 - r)); }
__device__ __forceinline__ void threefry2x32(uint32_t k0, uint32_t k1, uint32_t x0, uint32_t x1,
                                             uint32_t& o0, uint32_t& o1) {
    uint32_t k2 = k0 ^ k1 ^ 0x1BD11BDAu;
    x0 += k0; x1 += k1;
#define TF_R(a) x0 += x1; x1 = rotl32(x1, a); x1 ^= x0;
#define TF_G(a,b,c,d) TF_R(a) TF_R(b) TF_R(c) TF_R(d)
    TF_G(13, 15, 26, 6)  x0 += k1; x1 += k2 + 1u;
    TF_G(17, 29, 16, 24) x0 += k2; x1 += k0 + 2u;
    TF_G(13, 15, 26, 6)  x0 += k0; x1 += k1 + 3u;
    TF_G(17, 29, 16, 24) x0 += k1; x1 += k2 + 4u;
    TF_G(13, 15, 26, 6)  x0 += k2; x1 += k0 + 5u;
#undef TF_G
#undef TF_R
    o0 = x0; o1 = x1;
}
__device__ __forceinline__ float jax_normal_from_bits(uint32_t bits) {
    float u1 = __uint_as_float(0x3f800000u | (bits >> 9)) - 1.0f;
    const float lo = __uint_as_float(0xBF7FFFFFu);
    float u = __fadd_rn(__fmul_rn(u1, 2.0f), lo);
    u = fmaxf(u, lo);
    float w = -log1pf(-__fmul_rn(u, u));
    float p;
    if (w < 5.0f) {
        w = __fsub_rn(w, 2.5f);
        p = 2.81022636e-08f;
        p = __fmaf_rn(p, w, 3.43273939e-07f);
        p = __fmaf_rn(p, w, -3.5233877e-06f);
        p = __fmaf_rn(p, w, -4.39150654e-06f);
        p = __fmaf_rn(p, w, 0.00021858087f);
        p = __fmaf_rn(p, w, -0.00125372503f);
        p = __fmaf_rn(p, w, -0.00417768164f);
        p = __fmaf_rn(p, w, 0.246640727f);
        p = __fmaf_rn(p, w, 1.50140941f);
    } else {
        w = __fsub_rn(sqrtf(w), 3.0f);
        p = -0.000200214257f;
        p = __fmaf_rn(p, w, 0.000100950558f);
        p = __fmaf_rn(p, w, 0.00134934322f);
        p = __fmaf_rn(p, w, -0.00367342844f);
        p = __fmaf_rn(p, w, 0.00573950773f);
        p = __fmaf_rn(p, w, -0.0076224613f);
        p = __fmaf_rn(p, w, 0.00943887047f);
        p = __fmaf_rn(p, w, 1.00167406f);
        p = __fmaf_rn(p, w, 2.83297682f);
    }
    return __fmul_rn(__uint_as_float(0x3FB504F3u), __fmul_rn(p, u));
}
__device__ __forceinline__ float gen_normal_part(uint32_t k0, uint32_t k1, uint32_t i) {
    uint32_t o0, o1;
    threefry2x32(k0, k1, 0u, i, o0, o1);
    return jax_normal_from_bits(o0 ^ o1);
}

// ---- K1: router MLP ----
__global__ void __launch_bounds__(128) mlp_kernel(
    const float* __restrict__ phi, const float* __restrict__ w0, const float* __restrict__ b0,
    const float* __restrict__ w1, const float* __restrict__ b1, const float* __restrict__ w2,
    const float* __restrict__ b2, const float* __restrict__ noise_var, float* __restrict__ out) {
    __shared__ float sphi[512], sh[128], sh2[128], sl[12];
    int b = blockIdx.x, t = threadIdx.x;
    for (int d = t; d < 512; d += 128) sphi[d] = phi[b * 512 + d];
    __syncthreads();
    float a = 0.f;
    #pragma unroll 8
    for (int d = 0; d < 512; d++) a = __fmaf_rn(sphi[d], w0[d * 128 + t], a);
    sh[t] = fmaxf(__fadd_rn(a, b0[t]), 0.f);
    __syncthreads();
    float a2 = 0.f;
    #pragma unroll 8
    for (int i = 0; i < 128; i++) a2 = __fmaf_rn(sh[i], w1[i * 128 + t], a2);
    sh2[t] = fmaxf(__fadd_rn(a2, b1[t]), 0.f);
    __syncthreads();
    if (t < 12) {
        float l = 0.f;
        for (int i = 0; i < 128; i++) l = __fmaf_rn(sh2[i], w2[i * 12 + t], l);
        l = __fadd_rn(l, b2[t]);
        sl[t] = l;
        out[OFF_LOGITS + b * 12 + t] = l;
    }
    __syncthreads();
    if (t == 0) {
        float mx = sl[0]; int mi = 0;
        for (int j = 1; j < 12; j++) if (sl[j] > mx) { mx = sl[j]; mi = j; }
        float e[12], s = 0.f;
        for (int j = 0; j < 12; j++) { e[j] = expf(__fsub_rn(sl[j], mx)); s = __fadd_rn(s, e[j]); }
        for (int j = 0; j < 12; j++) out[OFF_PROBS + b * 12 + j] = __fdiv_rn(e[j], s);
        out[OFF_MODE + b] = (float)mi;
        g_expert[b] = mi / 3;
        g_phy[b] = mi % 3;
        if (b == 0) g_std = sqrtf(fmaxf(noise_var[0], 0.f));
    }
}

// ---- K2: fused row norms + bf16 conversion (sq ordering preserved exactly) ----
__global__ void __launch_bounds__(256) sq_kernel(const float* __restrict__ H,
                                                 const float* __restrict__ cb) {
    int warp = (blockIdx.x * blockDim.x + threadIdx.x) >> 5;
    int lane = threadIdx.x & 31;
    const int TOT = NB * NN + NR * NK;
    if (warp >= TOT) return;
    bool isH = (warp < NB * NN);
    const float* src = isH ? (H + (size_t)warp * NCH) : (cb + (size_t)(warp - NB * NN) * NCH);
    __nv_bfloat16* dst = isH ? (g_Hb + (size_t)warp * NCH)
                             : (g_cbb + (size_t)(warp - NB * NN) * NCH);
    double s = 0.0;
    #pragma unroll
    for (int c = lane; c < NCH; c += 32) {
        float v = src[c];
        s += (double)__fmul_rn(v, v);
        dst[c] = __float2bfloat16_rn(v);
    }
    #pragma unroll
    for (int o = 16; o; o >>= 1) s += __shfl_down_sync(0xffffffffu, s, o);
    if (lane == 0) { if (isH) g_zsq[warp] = (float)s; else g_cbsq[warp - NB * NN] = (float)s; }
}

// ---- K3: A-in-register bf16 mma, 32-col B chunks double-buffered, x4 B ldmatrix ----
#define PADK 264
#define BBUF 16896
#define S3_CBSQ 0
#define S3_CNT 4096
#define S3_B 4608
#define S3_TOT 38400

__global__ void __launch_bounds__(256, 2) vqm_kernel() {
    extern __shared__ char smem[];
    float* cbsq_s = (float*)(smem + S3_CBSQ);
    int* cnt_s = (int*)(smem + S3_CNT);
    uint32_t bBase = smem_to_u32(smem + S3_B);

    int tid = threadIdx.x, wid = tid >> 5, lane = tid & 31;
    int row0 = blockIdx.x * 128;
    int r = g_expert[row0 >> 10];
    for (int j = tid; j < 1024; j += 256) cbsq_s[j] = g_cbsq[r * 1024 + j];
    if (tid < 128) cnt_s[tid] = 0;

    uint32_t afrag[64];
    int arow_in = (lane & 7) + ((lane >> 3) & 1) * 8;
    int acolsel = (lane >> 4) * 8;
    #pragma unroll
    for (int it = 0; it < 8; it++) {
        int u = it * 256 + tid; int rr = u >> 5, kk = (u & 31) * 8;
        cp16(bBase + (uint32_t)(rr * PADK + kk) * 2, g_Hb + (size_t)(row0 + rr) * 256 + kk);
    }
    asm volatile("cp.async.commit_group;");
    asm volatile("cp.async.wait_group 0;");
    __syncthreads();
    if (wid < 4) {
        int br = wid * 16 + arow_in;
        #pragma unroll
        for (int k16 = 0; k16 < 16; k16++)
            ldmx4(&afrag[k16 * 4], bBase + (uint32_t)(br * PADK + k16 * 16 + acolsel) * 2);
    }
    __syncthreads();
    #pragma unroll
    for (int it = 0; it < 8; it++) {
        int u = it * 256 + tid; int rr = u >> 5, kk = (u & 31) * 8;
        cp16(bBase + (uint32_t)(rr * PADK + kk) * 2, g_Hb + (size_t)(row0 + 64 + rr) * 256 + kk);
    }
    asm volatile("cp.async.commit_group;");
    asm volatile("cp.async.wait_group 0;");
    __syncthreads();
    if (wid >= 4) {
        int br = (wid - 4) * 16 + arow_in;
        #pragma unroll
        for (int k16 = 0; k16 < 16; k16++)
            ldmx4(&afrag[k16 * 4], bBase + (uint32_t)(br * PADK + k16 * 16 + acolsel) * 2);
    }
    __syncthreads();

    int q = lane >> 2, s4 = lane & 3;
    int rowA = wid * 16 + q, rowB = rowA + 8;
    float z1 = g_zsq[row0 + rowA], z2 = g_zsq[row0 + rowB];
    float rmin1 = FMAXV, rmin2 = FMAXV;
    // x4 B-ldmatrix addressing: grp = lane>>3 (0..3), rowi = lane&7
    int grp = lane >> 3, rowi = lane & 7;
    int b_row_off = (grp >> 1) * 8 + rowi;     // row within the 16-row pair
    int b_col_off = (grp & 1) * 8;             // k half

    {
        uint32_t dst = bBase;
        #pragma unroll
        for (int it = 0; it < 4; it++) {
            int u = it * 256 + tid; int rr = u >> 5, kk = (u & 31) * 8;
            cp16(dst + (uint32_t)(rr * PADK + kk) * 2, g_cbb + (size_t)(r * 1024 + rr) * 256 + kk);
        }
        asm volatile("cp.async.commit_group;");
    }

    for (int ch = 0; ch < 32; ch++) {
        asm volatile("cp.async.wait_group 0;");
        __syncthreads();
        if (ch + 1 < 32) {
            uint32_t dst = bBase + (uint32_t)((ch + 1) & 1) * BBUF;
            #pragma unroll
            for (int it = 0; it < 4; it++) {
                int u = it * 256 + tid; int rr = u >> 5, kk = (u & 31) * 8;
                cp16(dst + (uint32_t)(rr * PADK + kk) * 2,
                     g_cbb + (size_t)(r * 1024 + (ch + 1) * 32 + rr) * 256 + kk);
            }
            asm volatile("cp.async.commit_group;");
        }
        uint32_t bcur = bBase + (uint32_t)(ch & 1) * BBUF;
        float acc[4][4];
        #pragma unroll
        for (int nf = 0; nf < 4; nf++)
            #pragma unroll
            for (int v = 0; v < 4; v++) acc[nf][v] = 0.f;
        #pragma unroll
        for (int k16 = 0; k16 < 16; k16++) {
            uint32_t bfr[8];
            #pragma unroll
            for (int np = 0; np < 2; np++)
                ldmx4(&bfr[np * 4],
                      bcur + (uint32_t)((np * 16 + b_row_off) * PADK + k16 * 16 + b_col_off) * 2);
            #pragma unroll
            for (int np = 0; np < 2; np++) {
                mma_bf16(acc[np * 2],     &afrag[k16 * 4], &bfr[np * 4]);
                mma_bf16(acc[np * 2 + 1], &afrag[k16 * 4], &bfr[np * 4 + 2]);
            }
        }
        float m1 = FMAXV, m2 = FMAXV;
        #pragma unroll
        for (int nf = 0; nf < 4; nf++) {
            #pragma unroll
            for (int v = 0; v < 2; v++) {
                float cq = cbsq_s[ch * 32 + nf * 8 + s4 * 2 + v];
                m1 = fminf(m1, __fmaf_rn(-2.f, acc[nf][v], __fadd_rn(z1, cq)));
                m2 = fminf(m2, __fmaf_rn(-2.f, acc[nf][v + 2], __fadd_rn(z2, cq)));
            }
        }
        m1 = fminf(m1, __shfl_xor_sync(0xffffffffu, m1, 1));
        m1 = fminf(m1, __shfl_xor_sync(0xffffffffu, m1, 2));
        m2 = fminf(m2, __shfl_xor_sync(0xffffffffu, m2, 1));
        m2 = fminf(m2, __shfl_xor_sync(0xffffffffu, m2, 2));
        rmin1 = fminf(rmin1, m1);
        rmin2 = fminf(rmin2, m2);
        float t1 = rmin1 + EPSF, t2 = rmin2 + EPSF;
        #pragma unroll
        for (int nf = 0; nf < 4; nf++) {
            #pragma unroll
            for (int v = 0; v < 2; v++) {
                int col = ch * 32 + nf * 8 + s4 * 2 + v;
                float cq = cbsq_s[col];
                float d1 = __fmaf_rn(-2.f, acc[nf][v], __fadd_rn(z1, cq));
                if (d1 <= t1) {
                    int pos = atomicAdd(&cnt_s[rowA], 1);
                    if (pos < CCAP) {
                        g_cand[(size_t)(row0 + rowA) * CCAP + pos] = col;
                        g_candd[(size_t)(row0 + rowA) * CCAP + pos] = d1;
                    }
                }
                float d2 = __fmaf_rn(-2.f, acc[nf][v + 2], __fadd_rn(z2, cq));
                if (d2 <= t2) {
                    int pos = atomicAdd(&cnt_s[rowB], 1);
                    if (pos < CCAP) {
                        g_cand[(size_t)(row0 + rowB) * CCAP + pos] = col;
                        g_candd[(size_t)(row0 + rowB) * CCAP + pos] = d2;
                    }
                }
            }
        }
    }
    __syncthreads();
    if (tid < 128) g_cc[row0 + tid] = cnt_s[tid];
}

// ---- K3b: re-rank + fused z_q/SSE/indices ----
__device__ __forceinline__ float seq_d(const float* __restrict__ z, const float* __restrict__ cr,
                                       float zsqv, float cbsqj) {
    float acc = 0.f;
    #pragma unroll 8
    for (int k = 0; k < 256; k++) acc = __fmaf_rn(z[k], cr[k], acc);
    return __fmaf_rn(-2.0f, acc, __fadd_rn(zsqv, cbsqj));
}
__global__ void __launch_bounds__(256) p2_kernel(const float* __restrict__ H,
                                                 const float* __restrict__ cb,
                                                 float* __restrict__ out) {
    __shared__ double ssep[8];
    int wid = threadIdx.x >> 5, lane = threadIdx.x & 31;
    int row = blockIdx.x * 8 + wid;
    int r = g_expert[row >> 10];
    const float* z = H + (size_t)row * 256;
    const float* cbase = cb + (size_t)r * 1024 * 256;
    const float* cbsq = g_cbsq + r * 1024;
    float zsqv = g_zsq[row];
    int c = g_cc[row];
    float best = FMAXV; int bestj = 0x7fffffff;
    if (c <= CCAP) {
        float dmin = FMAXV;
        for (int i0 = 0; i0 < c; i0 += 32) {
            float dv = (i0 + lane < c) ? g_candd[(size_t)row * CCAP + i0 + lane] : FMAXV;
            #pragma unroll
            for (int o = 16; o; o >>= 1) dv = fminf(dv, __shfl_xor_sync(0xffffffffu, dv, o));
            dmin = fminf(dmin, dv);
        }
        float thr = dmin + P2M;
        for (int i0 = 0; i0 < c; i0 += 32) {
            int idx = i0 + lane;
            float dv = (idx < c) ? g_candd[(size_t)row * CCAP + idx] : FMAXV;
            int j = (idx < c) ? g_cand[(size_t)row * CCAP + idx] : 0x7fffffff;
            float ds = FMAXV;
            if (dv <= thr) ds = seq_d(z, cbase + (size_t)j * 256, zsqv, cbsq[j]);
            else j = 0x7fffffff;
            #pragma unroll
            for (int o = 16; o; o >>= 1) {
                float od = __shfl_xor_sync(0xffffffffu, ds, o);
                int oj = __shfl_xor_sync(0xffffffffu, j, o);
                if (od < ds || (od == ds && oj < j)) { ds = od; j = oj; }
            }
            if (ds < best || (ds == best && j < bestj)) { best = ds; bestj = j; }
        }
    } else {
        for (int j0 = 0; j0 < 1024; j0 += 32) {
            int j = j0 + lane;
            float ds = seq_d(z, cbase + (size_t)j * 256, zsqv, cbsq[j]);
            #pragma unroll
            for (int o = 16; o; o >>= 1) {
                float od = __shfl_xor_sync(0xffffffffu, ds, o);
                int oj = __shfl_xor_sync(0xffffffffu, j, o);
                if (od < ds || (od == ds && oj < j)) { ds = od; j = oj; }
            }
            if (ds < best || (ds == best && j < bestj)) { best = ds; bestj = j; }
        }
    }
    if (lane == 0) {
        g_indices[row] = bestj;
        out[OFF_IND + row] = (float)bestj;
    }
    const float* cr = cbase + (size_t)bestj * 256;
    double acc = 0.0;
    #pragma unroll
    for (int t = 0; t < 8; t++) {
        int k = lane + 32 * t;
        float h = z[k];
        float dlt = __fsub_rn(cr[k], h);
        out[OFF_ZQ + (size_t)row * 256 + k] = __fadd_rn(h, dlt);
        acc += (double)__fmul_rn(dlt, dlt);
    }
    #pragma unroll
    for (int o = 16; o; o >>= 1) acc += __shfl_down_sync(0xffffffffu, acc, o);
    if (lane == 0) ssep[wid] = acc;
    __syncthreads();
    if (threadIdx.x == 0) {
        double s = 0.0;
        #pragma unroll
        for (int w = 0; w < 8; w++) s += ssep[w];
        g_ssep[blockIdx.x] = s;
    }
}

// ---- K5: QAM channel (symbol-parallel) ----
__global__ void __launch_bounds__(256) channel_kernel() {
    int b = blockIdx.x;
    int m = g_phy[b];
    int bps = (m == 0) ? 2 : (m == 1) ? 4 : 6;
    int n_sym = PADB / bps;
    int mside = (m == 0) ? 2 : (m == 1) ? 4 : 8;
    int M = mside * mside;
    float std_ = g_std;
    __shared__ float cx[64], cy[64];
    __shared__ uint32_t skey[2];
    if (threadIdx.x < M) {
        double mean = (m == 0) ? 2.0 : (m == 1) ? 10.0 : 42.0;
        double norm = sqrt(mean + 1e-9);
        int i = threadIdx.x / mside, j = threadIdx.x % mside;
        cx[threadIdx.x] = (float)((double)(-(mside - 1) + 2 * i) / norm);
        cy[threadIdx.x] = (float)((double)(-(mside - 1) + 2 * j) / norm);
    }
    if (threadIdx.x == 0) {
        uint32_t o0, o1;
        threefry2x32(0u, 42u, 0u, (uint32_t)m, o0, o1);
        skey[0] = o0; skey[1] = o1;
    }
    __syncthreads();
    int s = blockIdx.y * 256 + threadIdx.x;
    if (s >= n_sym) return;
    uint32_t k0 = skey[0], k1 = skey[1];
    const int* idxrow = g_indices + b * NN;
    uint8_t* bitrow = g_bits + b * PADB;
    int p0 = s * bps, sym = 0;
    for (int j = 0; j < bps; j++) {
        int p = p0 + j, bit = 0;
        if (p < TOTB) bit = (idxrow[p / 10] >> (9 - p % 10)) & 1;
        sym = (sym << 1) | bit;
    }
    float tx0 = cx[sym], tx1 = cy[sym];
    uint32_t i0 = (uint32_t)(b * n_sym + s) * 2u;
    float rx0 = __fadd_rn(tx0, __fmul_rn(std_, gen_normal_part(k0, k1, i0)));
    float rx1 = __fadd_rn(tx1, __fmul_rn(std_, gen_normal_part(k0, k1, i0 + 1u)));
    float best = FMAXV; int bi = 0;
    for (int k = 0; k < M; k++) {
        float dx = __fsub_rn(rx0, cx[k]), dy = __fsub_rn(rx1, cy[k]);
        float d = __fadd_rn(__fmul_rn(dx, dx), __fmul_rn(dy, dy));
        if (d < best) { best = d; bi = k; }
    }
    for (int j = 0; j < bps; j++)
        bitrow[p0 + j] = (uint8_t)((bi >> (bps - 1 - j)) & 1);
}

// ---- K6: idx_hat + H_hat + vq_loss (block 0 reduces SSE partials) ----
__global__ void __launch_bounds__(256) final_kernel(const float* __restrict__ H,
                                                    const float* __restrict__ cb,
                                                    float* __restrict__ out) {
    __shared__ int sidx[16];
    __shared__ double sred[256];
    int t = threadIdx.x;
    int row0 = blockIdx.x * 16;
    int b = row0 >> 10;
    int r = g_expert[b];
    if (t < 16) {
        int row = row0 + t;
        int n = row & (NN - 1);
        const uint8_t* bt = g_bits + b * PADB + n * 10;
        int v = 0;
        #pragma unroll
        for (int j = 0; j < 10; j++) v = (v << 1) | bt[j];
        if (v > NK - 1) v = NK - 1;
        sidx[t] = v;
        out[OFF_IDXHAT + row] = (float)v;
    }
    __syncthreads();
    #pragma unroll
    for (int it = 0; it < 4; it++) {
        int qid = it * 256 + t;
        int rl = qid >> 6, qq = qid & 63;
        size_t row = (size_t)row0 + rl;
        float4 h = reinterpret_cast<const float4*>(H)[row * 64 + qq];
        float4 c = reinterpret_cast<const float4*>(cb)[((size_t)r * 1024 + sidx[rl]) * 64 + qq];
        reinterpret_cast<float4*>(out + OFF_HHAT)[row * 64 + qq] =
            make_float4(__fadd_rn(h.x, __fsub_rn(c.x, h.x)), __fadd_rn(h.y, __fsub_rn(c.y, h.y)),
                        __fadd_rn(h.z, __fsub_rn(c.z, h.z)), __fadd_rn(h.w, __fsub_rn(c.w, h.w)));
    }
    if (blockIdx.x == 0) {
        double s = 0.0;
        for (int i = t; i < 8192; i += 256) s += g_ssep[i];
        sred[t] = s;
        __syncthreads();
        for (int st = 128; st; st >>= 1) {
            if (t < st) sred[t] += sred[t + st];
            __syncthreads();
        }
        if (t == 0) {
            double denom = (double)NB * (double)NN * (double)NCH * (double)NCH;
            out[OFF_VQ] = (float)(1.25 * sred[0] / denom);
        }
    }
}

// ---- launch ----
extern "C" void kernel_launch(void* const* d_in, const int* in_sizes, int n_in,
                              void* d_out, int out_size) {
    const float* H         = (const float*)d_in[0];
    const float* phi       = (const float*)d_in[1];
    const float* w0        = (const float*)d_in[2];
    const float* b0        = (const float*)d_in[3];
    const float* w1        = (const float*)d_in[4];
    const float* b1        = (const float*)d_in[5];
    const float* w2        = (const float*)d_in[6];
    const float* b2        = (const float*)d_in[7];
    const float* codebooks = (const float*)d_in[8];
    const float* noise_var = (const float*)d_in[9];
    float* out = (float*)d_out;

    cudaFuncSetAttribute(vqm_kernel, cudaFuncAttributeMaxDynamicSharedMemorySize, S3_TOT);

    mlp_kernel<<<NB, 128>>>(phi, w0, b0, w1, b1, w2, b2, noise_var, out);
    sq_kernel<<<(NB * NN + NR * NK + 7) / 8, 256>>>(H, codebooks);
    vqm_kernel<<<NB * NN / 128, 256, S3_TOT>>>();
    p2_kernel<<<NB * NN / 8, 256>>>(H, codebooks, out);
    channel_kernel<<<dim3(NB, 21), 256>>>();
    final_kernel<<<NB * NN / 16, 256>>>(H, codebooks, out);
}

// round 13
// speedup vs baseline: 2.5925x; 1.0959x over previous
#include <cuda_runtime.h>
#include <cuda_bf16.h>
#include <stdint.h>
#include <math.h>

#define NB 64
#define NN 1024
#define NCH 256
#define NR 4
#define NK 1024
#define TOTB 10240
#define PADB 10248
#define EPSF 0.25f
#define P2M  0.1f
#define CCAP 128
#define FMAXV 3.402823466e+38f

#define OFF_HHAT   0LL
#define OFF_ZQ     16777216LL
#define OFF_IND    33554432LL
#define OFF_IDXHAT 33619968LL
#define OFF_VQ     33685504LL
#define OFF_LOGITS 33685505LL
#define OFF_PROBS  33686273LL
#define OFF_MODE   33687041LL

__device__ int     g_expert[NB];
__device__ int     g_phy[NB];
__device__ float   g_std;
__device__ float   g_zsq[NB * NN];
__device__ float   g_cbsq[NR * NK];
__device__ int     g_indices[NB * NN];
__device__ uint8_t g_bits[NB * PADB];
__device__ double  g_ssep[8192];
__device__ __align__(16) __nv_bfloat16 g_Hb[NB * NN * NCH];
__device__ __align__(16) __nv_bfloat16 g_cbb[NR * NK * NCH];
__device__ int   g_cand[(size_t)NB * NN * CCAP];
__device__ float g_candd[(size_t)NB * NN * CCAP];
__device__ int   g_cc[NB * NN];

// ---- helpers ----
__device__ __forceinline__ uint32_t smem_to_u32(const void* p) {
    uint32_t a;
    asm("{ .reg .u64 t; cvta.to.shared.u64 t, %1; cvt.u32.u64 %0, t; }" : "=r"(a) : "l"(p));
    return a;
}
__device__ __forceinline__ void ldmx4(uint32_t* r, uint32_t addr) {
    asm volatile("ldmatrix.sync.aligned.m8n8.x4.shared.b16 {%0,%1,%2,%3}, [%4];"
        : "=r"(r[0]), "=r"(r[1]), "=r"(r[2]), "=r"(r[3]) : "r"(addr));
}
__device__ __forceinline__ void mma_bf16(float* c, const uint32_t* a, const uint32_t* b) {
    asm volatile("mma.sync.aligned.m16n8k16.row.col.f32.bf16.bf16.f32 "
        "{%0,%1,%2,%3}, {%4,%5,%6,%7}, {%8,%9}, {%0,%1,%2,%3};"
        : "+f"(c[0]), "+f"(c[1]), "+f"(c[2]), "+f"(c[3])
        : "r"(a[0]), "r"(a[1]), "r"(a[2]), "r"(a[3]), "r"(b[0]), "r"(b[1]));
}
__device__ __forceinline__ void cp16(uint32_t dst, const void* src) {
    asm volatile("cp.async.cg.shared.global [%0], [%1], 16;" :: "r"(dst), "l"(src));
}

// ---- threefry (JAX) ----
__device__ __forceinline__ uint32_t rotl32(uint32_t x, int r) { return (x << r) | (x >> (32 - r)); }
__device__ __forceinline__ void threefry2x32(uint32_t k0, uint32_t k1, uint32_t x0, uint32_t x1,
                                             uint32_t& o0, uint32_t& o1) {
    uint32_t k2 = k0 ^ k1 ^ 0x1BD11BDAu;
    x0 += k0; x1 += k1;
#define TF_R(a) x0 += x1; x1 = rotl32(x1, a); x1 ^= x0;
#define TF_G(a,b,c,d) TF_R(a) TF_R(b) TF_R(c) TF_R(d)
    TF_G(13, 15, 26, 6)  x0 += k1; x1 += k2 + 1u;
    TF_G(17, 29, 16, 24) x0 += k2; x1 += k0 + 2u;
    TF_G(13, 15, 26, 6)  x0 += k0; x1 += k1 + 3u;
    TF_G(17, 29, 16, 24) x0 += k1; x1 += k2 + 4u;
    TF_G(13, 15, 26, 6)  x0 += k2; x1 += k0 + 5u;
#undef TF_G
#undef TF_R
    o0 = x0; o1 = x1;
}
__device__ __forceinline__ float jax_normal_from_bits(uint32_t bits) {
    float u1 = __uint_as_float(0x3f800000u | (bits >> 9)) - 1.0f;
    const float lo = __uint_as_float(0xBF7FFFFFu);
    float u = __fadd_rn(__fmul_rn(u1, 2.0f), lo);
    u = fmaxf(u, lo);
    float w = -log1pf(-__fmul_rn(u, u));
    float p;
    if (w < 5.0f) {
        w = __fsub_rn(w, 2.5f);
        p = 2.81022636e-08f;
        p = __fmaf_rn(p, w, 3.43273939e-07f);
        p = __fmaf_rn(p, w, -3.5233877e-06f);
        p = __fmaf_rn(p, w, -4.39150654e-06f);
        p = __fmaf_rn(p, w, 0.00021858087f);
        p = __fmaf_rn(p, w, -0.00125372503f);
        p = __fmaf_rn(p, w, -0.00417768164f);
        p = __fmaf_rn(p, w, 0.246640727f);
        p = __fmaf_rn(p, w, 1.50140941f);
    } else {
        w = __fsub_rn(sqrtf(w), 3.0f);
        p = -0.000200214257f;
        p = __fmaf_rn(p, w, 0.000100950558f);
        p = __fmaf_rn(p, w, 0.00134934322f);
        p = __fmaf_rn(p, w, -0.00367342844f);
        p = __fmaf_rn(p, w, 0.00573950773f);
        p = __fmaf_rn(p, w, -0.0076224613f);
        p = __fmaf_rn(p, w, 0.00943887047f);
        p = __fmaf_rn(p, w, 1.00167406f);
        p = __fmaf_rn(p, w, 2.83297682f);
    }
    return __fmul_rn(__uint_as_float(0x3FB504F3u), __fmul_rn(p, u));
}
__device__ __forceinline__ float gen_normal_part(uint32_t k0, uint32_t k1, uint32_t i) {
    uint32_t o0, o1;
    threefry2x32(k0, k1, 0u, i, o0, o1);
    return jax_normal_from_bits(o0 ^ o1);
}

// ---- K1: router MLP ----
__global__ void __launch_bounds__(128) mlp_kernel(
    const float* __restrict__ phi, const float* __restrict__ w0, const float* __restrict__ b0,
    const float* __restrict__ w1, const float* __restrict__ b1, const float* __restrict__ w2,
    const float* __restrict__ b2, const float* __restrict__ noise_var, float* __restrict__ out) {
    __shared__ float sphi[512], sh[128], sh2[128], sl[12];
    int b = blockIdx.x, t = threadIdx.x;
    for (int d = t; d < 512; d += 128) sphi[d] = phi[b * 512 + d];
    __syncthreads();
    float a = 0.f;
    #pragma unroll 8
    for (int d = 0; d < 512; d++) a = __fmaf_rn(sphi[d], w0[d * 128 + t], a);
    sh[t] = fmaxf(__fadd_rn(a, b0[t]), 0.f);
    __syncthreads();
    float a2 = 0.f;
    #pragma unroll 8
    for (int i = 0; i < 128; i++) a2 = __fmaf_rn(sh[i], w1[i * 128 + t], a2);
    sh2[t] = fmaxf(__fadd_rn(a2, b1[t]), 0.f);
    __syncthreads();
    if (t < 12) {
        float l = 0.f;
        for (int i = 0; i < 128; i++) l = __fmaf_rn(sh2[i], w2[i * 12 + t], l);
        l = __fadd_rn(l, b2[t]);
        sl[t] = l;
        out[OFF_LOGITS + b * 12 + t] = l;
    }
    __syncthreads();
    if (t == 0) {
        float mx = sl[0]; int mi = 0;
        for (int j = 1; j < 12; j++) if (sl[j] > mx) { mx = sl[j]; mi = j; }
        float e[12], s = 0.f;
        for (int j = 0; j < 12; j++) { e[j] = expf(__fsub_rn(sl[j], mx)); s = __fadd_rn(s, e[j]); }
        for (int j = 0; j < 12; j++) out[OFF_PROBS + b * 12 + j] = __fdiv_rn(e[j], s);
        out[OFF_MODE + b] = (float)mi;
        g_expert[b] = mi / 3;
        g_phy[b] = mi % 3;
        if (b == 0) g_std = sqrtf(fmaxf(noise_var[0], 0.f));
    }
}

// ---- K2: fused row norms + bf16 conversion (sq ordering preserved exactly) ----
__global__ void __launch_bounds__(256) sq_kernel(const float* __restrict__ H,
                                                 const float* __restrict__ cb) {
    int warp = (blockIdx.x * blockDim.x + threadIdx.x) >> 5;
    int lane = threadIdx.x & 31;
    const int TOT = NB * NN + NR * NK;
    if (warp >= TOT) return;
    bool isH = (warp < NB * NN);
    const float* src = isH ? (H + (size_t)warp * NCH) : (cb + (size_t)(warp - NB * NN) * NCH);
    __nv_bfloat16* dst = isH ? (g_Hb + (size_t)warp * NCH)
                             : (g_cbb + (size_t)(warp - NB * NN) * NCH);
    double s = 0.0;
    #pragma unroll
    for (int c = lane; c < NCH; c += 32) {
        float v = src[c];
        s += (double)__fmul_rn(v, v);
        dst[c] = __float2bfloat16_rn(v);
    }
    #pragma unroll
    for (int o = 16; o; o >>= 1) s += __shfl_down_sync(0xffffffffu, s, o);
    if (lane == 0) { if (isH) g_zsq[warp] = (float)s; else g_cbsq[warp - NB * NN] = (float)s; }
}

// ---- K3: A-in-register bf16 mma, 32-col B chunks double-buffered, x4 B ldmatrix ----
#define PADK 264
#define BBUF 16896
#define S3_CBSQ 0
#define S3_CNT 4096
#define S3_B 4608
#define S3_TOT 38400

__global__ void __launch_bounds__(256, 2) vqm_kernel() {
    extern __shared__ char smem[];
    float* cbsq_s = (float*)(smem + S3_CBSQ);
    int* cnt_s = (int*)(smem + S3_CNT);
    uint32_t bBase = smem_to_u32(smem + S3_B);

    int tid = threadIdx.x, wid = tid >> 5, lane = tid & 31;
    int row0 = blockIdx.x * 128;
    int r = g_expert[row0 >> 10];
    for (int j = tid; j < 1024; j += 256) cbsq_s[j] = g_cbsq[r * 1024 + j];
    if (tid < 128) cnt_s[tid] = 0;

    uint32_t afrag[64];
    int arow_in = (lane & 7) + ((lane >> 3) & 1) * 8;
    int acolsel = (lane >> 4) * 8;
    #pragma unroll
    for (int it = 0; it < 8; it++) {
        int u = it * 256 + tid; int rr = u >> 5, kk = (u & 31) * 8;
        cp16(bBase + (uint32_t)(rr * PADK + kk) * 2, g_Hb + (size_t)(row0 + rr) * 256 + kk);
    }
    asm volatile("cp.async.commit_group;");
    asm volatile("cp.async.wait_group 0;");
    __syncthreads();
    if (wid < 4) {
        int br = wid * 16 + arow_in;
        #pragma unroll
        for (int k16 = 0; k16 < 16; k16++)
            ldmx4(&afrag[k16 * 4], bBase + (uint32_t)(br * PADK + k16 * 16 + acolsel) * 2);
    }
    __syncthreads();
    #pragma unroll
    for (int it = 0; it < 8; it++) {
        int u = it * 256 + tid; int rr = u >> 5, kk = (u & 31) * 8;
        cp16(bBase + (uint32_t)(rr * PADK + kk) * 2, g_Hb + (size_t)(row0 + 64 + rr) * 256 + kk);
    }
    asm volatile("cp.async.commit_group;");
    asm volatile("cp.async.wait_group 0;");
    __syncthreads();
    if (wid >= 4) {
        int br = (wid - 4) * 16 + arow_in;
        #pragma unroll
        for (int k16 = 0; k16 < 16; k16++)
            ldmx4(&afrag[k16 * 4], bBase + (uint32_t)(br * PADK + k16 * 16 + acolsel) * 2);
    }
    __syncthreads();

    int q = lane >> 2, s4 = lane & 3;
    int rowA = wid * 16 + q, rowB = rowA + 8;
    float z1 = g_zsq[row0 + rowA], z2 = g_zsq[row0 + rowB];
    float rmin1 = FMAXV, rmin2 = FMAXV;
    int grp = lane >> 3, rowi = lane & 7;
    int b_row_off = (grp >> 1) * 8 + rowi;
    int b_col_off = (grp & 1) * 8;

    {
        uint32_t dst = bBase;
        #pragma unroll
        for (int it = 0; it < 4; it++) {
            int u = it * 256 + tid; int rr = u >> 5, kk = (u & 31) * 8;
            cp16(dst + (uint32_t)(rr * PADK + kk) * 2, g_cbb + (size_t)(r * 1024 + rr) * 256 + kk);
        }
        asm volatile("cp.async.commit_group;");
    }

    for (int ch = 0; ch < 32; ch++) {
        asm volatile("cp.async.wait_group 0;");
        __syncthreads();
        if (ch + 1 < 32) {
            uint32_t dst = bBase + (uint32_t)((ch + 1) & 1) * BBUF;
            #pragma unroll
            for (int it = 0; it < 4; it++) {
                int u = it * 256 + tid; int rr = u >> 5, kk = (u & 31) * 8;
                cp16(dst + (uint32_t)(rr * PADK + kk) * 2,
                     g_cbb + (size_t)(r * 1024 + (ch + 1) * 32 + rr) * 256 + kk);
            }
            asm volatile("cp.async.commit_group;");
        }
        uint32_t bcur = bBase + (uint32_t)(ch & 1) * BBUF;
        float acc[4][4];
        #pragma unroll
        for (int nf = 0; nf < 4; nf++)
            #pragma unroll
            for (int v = 0; v < 4; v++) acc[nf][v] = 0.f;
        #pragma unroll
        for (int k16 = 0; k16 < 16; k16++) {
            uint32_t bfr[8];
            #pragma unroll
            for (int np = 0; np < 2; np++)
                ldmx4(&bfr[np * 4],
                      bcur + (uint32_t)((np * 16 + b_row_off) * PADK + k16 * 16 + b_col_off) * 2);
            #pragma unroll
            for (int np = 0; np < 2; np++) {
                mma_bf16(acc[np * 2],     &afrag[k16 * 4], &bfr[np * 4]);
                mma_bf16(acc[np * 2 + 1], &afrag[k16 * 4], &bfr[np * 4 + 2]);
            }
        }
        float m1 = FMAXV, m2 = FMAXV;
        #pragma unroll
        for (int nf = 0; nf < 4; nf++) {
            #pragma unroll
            for (int v = 0; v < 2; v++) {
                float cq = cbsq_s[ch * 32 + nf * 8 + s4 * 2 + v];
                m1 = fminf(m1, __fmaf_rn(-2.f, acc[nf][v], __fadd_rn(z1, cq)));
                m2 = fminf(m2, __fmaf_rn(-2.f, acc[nf][v + 2], __fadd_rn(z2, cq)));
            }
        }
        m1 = fminf(m1, __shfl_xor_sync(0xffffffffu, m1, 1));
        m1 = fminf(m1, __shfl_xor_sync(0xffffffffu, m1, 2));
        m2 = fminf(m2, __shfl_xor_sync(0xffffffffu, m2, 1));
        m2 = fminf(m2, __shfl_xor_sync(0xffffffffu, m2, 2));
        rmin1 = fminf(rmin1, m1);
        rmin2 = fminf(rmin2, m2);
        float t1 = rmin1 + EPSF, t2 = rmin2 + EPSF;
        #pragma unroll
        for (int nf = 0; nf < 4; nf++) {
            #pragma unroll
            for (int v = 0; v < 2; v++) {
                int col = ch * 32 + nf * 8 + s4 * 2 + v;
                float cq = cbsq_s[col];
                float d1 = __fmaf_rn(-2.f, acc[nf][v], __fadd_rn(z1, cq));
                if (d1 <= t1) {
                    int pos = atomicAdd(&cnt_s[rowA], 1);
                    if (pos < CCAP) {
                        g_cand[(size_t)(row0 + rowA) * CCAP + pos] = col;
                        g_candd[(size_t)(row0 + rowA) * CCAP + pos] = d1;
                    }
                }
                float d2 = __fmaf_rn(-2.f, acc[nf][v + 2], __fadd_rn(z2, cq));
                if (d2 <= t2) {
                    int pos = atomicAdd(&cnt_s[rowB], 1);
                    if (pos < CCAP) {
                        g_cand[(size_t)(row0 + rowB) * CCAP + pos] = col;
                        g_candd[(size_t)(row0 + rowB) * CCAP + pos] = d2;
                    }
                }
            }
        }
    }
    __syncthreads();
    if (tid < 128) g_cc[row0 + tid] = cnt_s[tid];
}

// ---- K3b: re-rank + fused z_q/SSE/indices, single-candidate fast path ----
__device__ __forceinline__ float seq_d(const float* __restrict__ z, const float* __restrict__ cr,
                                       float zsqv, float cbsqj) {
    float acc = 0.f;
    #pragma unroll 8
    for (int k = 0; k < 256; k++) acc = __fmaf_rn(z[k], cr[k], acc);
    return __fmaf_rn(-2.0f, acc, __fadd_rn(zsqv, cbsqj));
}
__global__ void __launch_bounds__(256) p2_kernel(const float* __restrict__ H,
                                                 const float* __restrict__ cb,
                                                 float* __restrict__ out) {
    __shared__ double ssep[8];
    int wid = threadIdx.x >> 5, lane = threadIdx.x & 31;
    int row = blockIdx.x * 8 + wid;
    int r = g_expert[row >> 10];
    const float* z = H + (size_t)row * 256;
    const float* cbase = cb + (size_t)r * 1024 * 256;
    const float* cbsq = g_cbsq + r * 1024;
    float zsqv = g_zsq[row];
    int c = g_cc[row];
    float best = FMAXV; int bestj = 0x7fffffff;
    if (c <= CCAP) {
        // pass A: min of stored approx distances
        float dmin = FMAXV;
        for (int i0 = 0; i0 < c; i0 += 32) {
            float dv = (i0 + lane < c) ? g_candd[(size_t)row * CCAP + i0 + lane] : FMAXV;
            #pragma unroll
            for (int o = 16; o; o >>= 1) dv = fminf(dv, __shfl_xor_sync(0xffffffffu, dv, o));
            dmin = fminf(dmin, dv);
        }
        float thr = dmin + P2M;
        // pass A': count in-window candidates and their min index
        int nwin = 0, jwin = 0x7fffffff;
        for (int i0 = 0; i0 < c; i0 += 32) {
            int idx = i0 + lane;
            bool p = false; int j = 0x7fffffff;
            if (idx < c) {
                float dv = g_candd[(size_t)row * CCAP + idx];
                if (dv <= thr) { p = true; j = g_cand[(size_t)row * CCAP + idx]; }
            }
            uint32_t mask = __ballot_sync(0xffffffffu, p);
            nwin += __popc(mask);
            #pragma unroll
            for (int o = 16; o; o >>= 1) j = min(j, __shfl_xor_sync(0xffffffffu, j, o));
            jwin = min(jwin, j);
        }
        if (nwin == 1) {
            bestj = jwin;   // identical to seq_d path by construction
        } else {
            for (int i0 = 0; i0 < c; i0 += 32) {
                int idx = i0 + lane;
                float dv = (idx < c) ? g_candd[(size_t)row * CCAP + idx] : FMAXV;
                int j = (idx < c) ? g_cand[(size_t)row * CCAP + idx] : 0x7fffffff;
                float ds = FMAXV;
                if (dv <= thr) ds = seq_d(z, cbase + (size_t)j * 256, zsqv, cbsq[j]);
                else j = 0x7fffffff;
                #pragma unroll
                for (int o = 16; o; o >>= 1) {
                    float od = __shfl_xor_sync(0xffffffffu, ds, o);
                    int oj = __shfl_xor_sync(0xffffffffu, j, o);
                    if (od < ds || (od == ds && oj < j)) { ds = od; j = oj; }
                }
                if (ds < best || (ds == best && j < bestj)) { best = ds; bestj = j; }
            }
        }
    } else {
        for (int j0 = 0; j0 < 1024; j0 += 32) {
            int j = j0 + lane;
            float ds = seq_d(z, cbase + (size_t)j * 256, zsqv, cbsq[j]);
            #pragma unroll
            for (int o = 16; o; o >>= 1) {
                float od = __shfl_xor_sync(0xffffffffu, ds, o);
                int oj = __shfl_xor_sync(0xffffffffu, j, o);
                if (od < ds || (od == ds && oj < j)) { ds = od; j = oj; }
            }
            if (ds < best || (ds == best && j < bestj)) { best = ds; bestj = j; }
        }
    }
    if (lane == 0) {
        g_indices[row] = bestj;
        out[OFF_IND + row] = (float)bestj;
    }
    bestj = __shfl_sync(0xffffffffu, bestj, 0);
    const float* cr = cbase + (size_t)bestj * 256;
    double acc = 0.0;
    #pragma unroll
    for (int t = 0; t < 8; t++) {
        int k = lane + 32 * t;
        float h = z[k];
        float dlt = __fsub_rn(cr[k], h);
        out[OFF_ZQ + (size_t)row * 256 + k] = __fadd_rn(h, dlt);
        acc += (double)__fmul_rn(dlt, dlt);
    }
    #pragma unroll
    for (int o = 16; o; o >>= 1) acc += __shfl_down_sync(0xffffffffu, acc, o);
    if (lane == 0) ssep[wid] = acc;
    __syncthreads();
    if (threadIdx.x == 0) {
        double s = 0.0;
        #pragma unroll
        for (int w = 0; w < 8; w++) s += ssep[w];
        g_ssep[blockIdx.x] = s;
    }
}

// ---- K5: QAM channel (symbol-parallel) ----
__global__ void __launch_bounds__(256) channel_kernel() {
    int b = blockIdx.x;
    int m = g_phy[b];
    int bps = (m == 0) ? 2 : (m == 1) ? 4 : 6;
    int n_sym = PADB / bps;
    int mside = (m == 0) ? 2 : (m == 1) ? 4 : 8;
    int M = mside * mside;
    float std_ = g_std;
    __shared__ float cx[64], cy[64];
    __shared__ uint32_t skey[2];
    if (threadIdx.x < M) {
        double mean = (m == 0) ? 2.0 : (m == 1) ? 10.0 : 42.0;
        double norm = sqrt(mean + 1e-9);
        int i = threadIdx.x / mside, j = threadIdx.x % mside;
        cx[threadIdx.x] = (float)((double)(-(mside - 1) + 2 * i) / norm);
        cy[threadIdx.x] = (float)((double)(-(mside - 1) + 2 * j) / norm);
    }
    if (threadIdx.x == 0) {
        uint32_t o0, o1;
        threefry2x32(0u, 42u, 0u, (uint32_t)m, o0, o1);
        skey[0] = o0; skey[1] = o1;
    }
    __syncthreads();
    int s = blockIdx.y * 256 + threadIdx.x;
    if (s >= n_sym) return;
    uint32_t k0 = skey[0], k1 = skey[1];
    const int* idxrow = g_indices + b * NN;
    uint8_t* bitrow = g_bits + b * PADB;
    int p0 = s * bps, sym = 0;
    for (int j = 0; j < bps; j++) {
        int p = p0 + j, bit = 0;
        if (p < TOTB) bit = (idxrow[p / 10] >> (9 - p % 10)) & 1;
        sym = (sym << 1) | bit;
    }
    float tx0 = cx[sym], tx1 = cy[sym];
    uint32_t i0 = (uint32_t)(b * n_sym + s) * 2u;
    float rx0 = __fadd_rn(tx0, __fmul_rn(std_, gen_normal_part(k0, k1, i0)));
    float rx1 = __fadd_rn(tx1, __fmul_rn(std_, gen_normal_part(k0, k1, i0 + 1u)));
    float best = FMAXV; int bi = 0;
    for (int k = 0; k < M; k++) {
        float dx = __fsub_rn(rx0, cx[k]), dy = __fsub_rn(rx1, cy[k]);
        float d = __fadd_rn(__fmul_rn(dx, dx), __fmul_rn(dy, dy));
        if (d < best) { best = d; bi = k; }
    }
    for (int j = 0; j < bps; j++)
        bitrow[p0 + j] = (uint8_t)((bi >> (bps - 1 - j)) & 1);
}

// ---- K6: idx_hat + H_hat + vq_loss ----
__global__ void __launch_bounds__(256) final_kernel(const float* __restrict__ H,
                                                    const float* __restrict__ cb,
                                                    float* __restrict__ out) {
    __shared__ int sidx[16];
    __shared__ double sred[256];
    int t = threadIdx.x;
    int row0 = blockIdx.x * 16;
    int b = row0 >> 10;
    int r = g_expert[b];
    if (t < 16) {
        int row = row0 + t;
        int n = row & (NN - 1);
        const uint8_t* bt = g_bits + b * PADB + n * 10;
        int v = 0;
        #pragma unroll
        for (int j = 0; j < 10; j++) v = (v << 1) | bt[j];
        if (v > NK - 1) v = NK - 1;
        sidx[t] = v;
        out[OFF_IDXHAT + row] = (float)v;
    }
    __syncthreads();
    #pragma unroll
    for (int it = 0; it < 4; it++) {
        int qid = it * 256 + t;
        int rl = qid >> 6, qq = qid & 63;
        size_t row = (size_t)row0 + rl;
        float4 h = reinterpret_cast<const float4*>(H)[row * 64 + qq];
        float4 c = reinterpret_cast<const float4*>(cb)[((size_t)r * 1024 + sidx[rl]) * 64 + qq];
        reinterpret_cast<float4*>(out + OFF_HHAT)[row * 64 + qq] =
            make_float4(__fadd_rn(h.x, __fsub_rn(c.x, h.x)), __fadd_rn(h.y, __fsub_rn(c.y, h.y)),
                        __fadd_rn(h.z, __fsub_rn(c.z, h.z)), __fadd_rn(h.w, __fsub_rn(c.w, h.w)));
    }
    if (blockIdx.x == 0) {
        double s = 0.0;
        for (int i = t; i < 8192; i += 256) s += g_ssep[i];
        sred[t] = s;
        __syncthreads();
        for (int st = 128; st; st >>= 1) {
            if (t < st) sred[t] += sred[t + st];
            __syncthreads();
        }
        if (t == 0) {
            double denom = (double)NB * (double)NN * (double)NCH * (double)NCH;
            out[OFF_VQ] = (float)(1.25 * sred[0] / denom);
        }
    }
}

// ---- launch ----
extern "C" void kernel_launch(void* const* d_in, const int* in_sizes, int n_in,
                              void* d_out, int out_size) {
    const float* H         = (const float*)d_in[0];
    const float* phi       = (const float*)d_in[1];
    const float* w0        = (const float*)d_in[2];
    const float* b0        = (const float*)d_in[3];
    const float* w1        = (const float*)d_in[4];
    const float* b1        = (const float*)d_in[5];
    const float* w2        = (const float*)d_in[6];
    const float* b2        = (const float*)d_in[7];
    const float* codebooks = (const float*)d_in[8];
    const float* noise_var = (const float*)d_in[9];
    float* out = (float*)d_out;

    cudaFuncSetAttribute(vqm_kernel, cudaFuncAttributeMaxDynamicSharedMemorySize, S3_TOT);

    mlp_kernel<<<NB, 128>>>(phi, w0, b0, w1, b1, w2, b2, noise_var, out);
    sq_kernel<<<(NB * NN + NR * NK + 7) / 8, 256>>>(H, codebooks);
    vqm_kernel<<<NB * NN / 128, 256, S3_TOT>>>();
    p2_kernel<<<NB * NN / 8, 256>>>(H, codebooks, out);
    channel_kernel<<<dim3(NB, 21), 256>>>();
    final_kernel<<<NB * NN / 16, 256>>>(H, codebooks, out);
}